// round 8
// baseline (speedup 1.0000x reference)
#include <cuda_runtime.h>
#include <math.h>

#define BB 8
#define NN 8192
#define SS 2048
#define KK 32
#define RAD 0.2f
#define EPSV 1e-5f

// NO __device__ globals, NO scratch buffers anywhere in this module.
// All intermediate state lives in d_out itself:
//   out[0 .. B*S*3)              = new_xyz (written by fps)
//   out[B*S*3 ..]                = out_feat rows of 128 floats per query;
//                                  bq temporarily stores 32 neighbor ints at the
//                                  head of each row, mlp reads then overwrites.

// ---------------- farthest point sampling: points in SHARED memory ----------------
#define FPS_T 1024
#define FPS_P 8
#define FPS_SMEM_BYTES (3 * NN * (int)sizeof(float))
__global__ void __launch_bounds__(FPS_T) fps_kernel(const float* __restrict__ xyz,
                                                    float* __restrict__ out_xyz)
{
    extern __shared__ float fsm[];
    float* sx = fsm;
    float* sy = fsm + NN;
    float* sz = fsm + 2 * NN;
    __shared__ float s_val[32];
    __shared__ int   s_idx[32];
    __shared__ int   s_win;

    const int b = blockIdx.x, tid = threadIdx.x;
    const float* X = xyz + (size_t)b * NN * 3;
    for (int i = tid; i < NN; i += FPS_T) {
        sx[i] = X[3 * i + 0];
        sy[i] = X[3 * i + 1];
        sz[i] = X[3 * i + 2];
    }
    float mind[FPS_P];
#pragma unroll
    for (int j = 0; j < FPS_P; j++) mind[j] = 1e10f;

    if (tid == 0) {
        float* o = out_xyz + (size_t)b * SS * 3;
        o[0] = X[0]; o[1] = X[1]; o[2] = X[2];   // sample 0 = index 0
    }
    __syncthreads();

    const int lane = tid & 31, warp = tid >> 5;  // 32 warps
    int w = 0;
    for (int s = 1; s < SS; s++) {
        const float lx = sx[w], ly = sy[w], lz = sz[w];   // smem broadcast
        float best = -1.0f; int bidx = 0;
#pragma unroll
        for (int j = 0; j < FPS_P; j++) {
            int i = j * FPS_T + tid;
            float dx = __fadd_rn(sx[i], -lx);
            float dy = __fadd_rn(sy[i], -ly);
            float dz = __fadd_rn(sz[i], -lz);
            float d = __fadd_rn(__fadd_rn(__fmul_rn(dx, dx), __fmul_rn(dy, dy)), __fmul_rn(dz, dz));
            float m = fminf(mind[j], d);
            mind[j] = m;
            if (m > best) { best = m; bidx = i; }   // strict >: lowest index on tie
        }
#pragma unroll
        for (int off = 16; off > 0; off >>= 1) {
            float ov = __shfl_xor_sync(0xffffffffu, best, off);
            int   oi = __shfl_xor_sync(0xffffffffu, bidx, off);
            if (ov > best || (ov == best && oi < bidx)) { best = ov; bidx = oi; }
        }
        if (lane == 0) { s_val[warp] = best; s_idx[warp] = bidx; }
        __syncthreads();
        if (warp == 0) {
            float v = s_val[lane]; int i = s_idx[lane];
#pragma unroll
            for (int off = 16; off > 0; off >>= 1) {
                float ov = __shfl_xor_sync(0xffffffffu, v, off);
                int   oi = __shfl_xor_sync(0xffffffffu, i, off);
                if (ov > v || (ov == v && oi < i)) { v = ov; i = oi; }
            }
            if (lane == 0) s_win = i;
        }
        __syncthreads();
        w = s_win;
        if (tid == 0) {
            float* o = out_xyz + ((size_t)b * SS + s) * 3;
            o[0] = sx[w]; o[1] = sy[w]; o[2] = sz[w];
        }
    }
}

// ---------------- ball query: top-32 in SMEM; neighbor ints -> head of output row ----------------
#define BQ_T 128
#define BQ_TILE 1024
__global__ void __launch_bounds__(BQ_T) bq_kernel(const float* __restrict__ xyz,
                                                  const float* __restrict__ newxyz,
                                                  float* __restrict__ out_feat)
{
    const int b = blockIdx.y;
    const int s = blockIdx.x * BQ_T + threadIdx.x;
    const int tid = threadIdx.x;
    const float* X = xyz + (size_t)b * NN * 3;

    __shared__ float4 sp[BQ_TILE];                 // 16 KB point tile (xyz, |p|^2)
    __shared__ float  sd[KK * BQ_T];               // 16 KB keys   sd[j*BQ_T + tid]
    __shared__ int    sid[KK * BQ_T];              // 16 KB indices

#pragma unroll
    for (int j = 0; j < KK; j++) { sd[j * BQ_T + tid] = 3.4e38f; sid[j * BQ_T + tid] = 0; }

    const float qx = newxyz[((size_t)b * SS + s) * 3 + 0];
    const float qy = newxyz[((size_t)b * SS + s) * 3 + 1];
    const float qz = newxyz[((size_t)b * SS + s) * 3 + 2];
    const float a2 = __fadd_rn(__fadd_rn(__fmul_rn(qx, qx), __fmul_rn(qy, qy)), __fmul_rn(qz, qz));

    float worst = 3.4e38f;
    for (int t0 = 0; t0 < NN; t0 += BQ_TILE) {
        __syncthreads();
        for (int i = tid; i < BQ_TILE; i += BQ_T) {
            float x = X[(t0 + i) * 3 + 0];
            float y = X[(t0 + i) * 3 + 1];
            float z = X[(t0 + i) * 3 + 2];
            float b2 = __fadd_rn(__fadd_rn(__fmul_rn(x, x), __fmul_rn(y, y)), __fmul_rn(z, z));
            sp[i] = make_float4(x, y, z, b2);
        }
        __syncthreads();
#pragma unroll 4
        for (int i = 0; i < BQ_TILE; i++) {
            float4 p = sp[i];
            float ab = __fadd_rn(__fadd_rn(__fmul_rn(qx, p.x), __fmul_rn(qy, p.y)), __fmul_rn(qz, p.z));
            float key = fmaxf(__fadd_rn(__fadd_rn(a2, p.w), __fmul_rn(-2.0f, ab)), 0.0f);
            if (key < worst) {                                // strict <: stable ties by index
                int j = KK - 1;
                while (j > 0) {
                    float pj = sd[(j - 1) * BQ_T + tid];
                    if (pj <= key) break;
                    sd[j * BQ_T + tid]  = pj;
                    sid[j * BQ_T + tid] = sid[(j - 1) * BQ_T + tid];
                    --j;
                }
                sd[j * BQ_T + tid]  = key;
                sid[j * BQ_T + tid] = t0 + i;
                worst = sd[(KK - 1) * BQ_T + tid];
            }
        }
    }
    // stash neighbor ints at the head of this query's 128-float output row
    int* nbrow = (int*)(out_feat + (size_t)(b * SS + s) * 128);
#pragma unroll
    for (int j = 0; j < KK; j++) {
        float dist = __fsqrt_rn(sd[j * BQ_T + tid]);
        nbrow[j] = (dist < RAD) ? sid[j * BQ_T + tid] : 0;  // -1 sentinel clamps to 0 anyway
    }
}

// ---------------- fused MLP: fold BN in smem, gather, 3 layers, max pool ----------------
// warp = query, lane = neighbor. Per-lane activations in smem columns [c][tid]
// (stride 128 -> own bank, same-thread only -> no syncs after weight fold).
// Accumulator chunks of 32 keep live regs ~55 (255-reg cap at 128 threads).
#define MLP_SMEM_FLOATS (4288 + 4096 + 8192 + 256 + 256 + 8192 + 8192)
__global__ void __launch_bounds__(128) mlp_kernel(
    const float* __restrict__ xyz, const float* __restrict__ feat,
    const float* __restrict__ W0, const float* __restrict__ b0, const float* __restrict__ gg0,
    const float* __restrict__ be0, const float* __restrict__ m0, const float* __restrict__ v0,
    const float* __restrict__ W1, const float* __restrict__ b1, const float* __restrict__ gg1,
    const float* __restrict__ be1, const float* __restrict__ m1, const float* __restrict__ v1,
    const float* __restrict__ W2, const float* __restrict__ b2, const float* __restrict__ gg2,
    const float* __restrict__ be2, const float* __restrict__ m2, const float* __restrict__ v2,
    const float* __restrict__ newxyz, float* __restrict__ out_feat)
{
    extern __shared__ float dsm[];
    float* sW0T = dsm;                 // 4288  [c<67][o<64] folded
    float* sW1T = sW0T + 4288;         // 4096  [c][o]
    float* sW2T = sW1T + 4096;         // 8192  [c][o<128]
    float* sC   = sW2T + 8192;         // 256: C0[64] C1[64] C2[128]
    float* sS   = sC + 256;            // 256: s0[64] s1[64] s2[128]
    float* sF   = sS + 256;            // 8192  [c][tid] feats, later h1
    float* sH   = sF + 8192;           // 8192  [c][tid] h0

    const int t = threadIdx.x;
    if (t < 64) {
        float s0 = gg0[t] / sqrtf(v0[t] + EPSV);
        float s1 = gg1[t] / sqrtf(v1[t] + EPSV);
        sS[t] = s0; sS[64 + t] = s1;
        sC[t] = (b0[t] - m0[t]) * s0 + be0[t];
        sC[64 + t] = (b1[t] - m1[t]) * s1 + be1[t];
    }
    if (t < 128) {
        float s2 = gg2[t] / sqrtf(v2[t] + EPSV);
        sS[128 + t] = s2;
        sC[128 + t] = (b2[t] - m2[t]) * s2 + be2[t];
    }
    __syncthreads();
    for (int i = t; i < 67 * 64; i += 128)  { int c = i >> 6, o = i & 63;  sW0T[i] = W0[o * 67 + c] * sS[o]; }
    for (int i = t; i < 64 * 64; i += 128)  { int c = i >> 6, o = i & 63;  sW1T[i] = W1[o * 64 + c] * sS[64 + o]; }
    for (int i = t; i < 64 * 128; i += 128) { int c = i >> 7, o = i & 127; sW2T[i] = W2[o * 64 + c] * sS[128 + o]; }
    __syncthreads();

    const int warp = t >> 5, lane = t & 31;
    const int q = blockIdx.x * 4 + warp;
    const int b = q >> 11;
    const float nx = newxyz[(size_t)q * 3], ny = newxyz[(size_t)q * 3 + 1], nz = newxyz[(size_t)q * 3 + 2];
    float* orow = out_feat + (size_t)q * 128;

    // read this lane's neighbor index BEFORE any write to the row
    const int nbi = ((const int*)orow)[lane];
    const float* prow = xyz + ((size_t)b * NN + nbi) * 3;
    const float dx = prow[0] - nx, dy = prow[1] - ny, dz = prow[2] - nz;
    const float* frow = feat + ((size_t)b * NN + nbi) * 64;
#pragma unroll
    for (int c = 0; c < 64; c += 4) {
        float4 v = *(const float4*)(frow + c);
        sF[(c + 0) * 128 + t] = v.x;
        sF[(c + 1) * 128 + t] = v.y;
        sF[(c + 2) * 128 + t] = v.z;
        sF[(c + 3) * 128 + t] = v.w;
    }

    // ---- layer 0: 67 -> 64, two halves of 32 outputs ----
#pragma unroll 1
    for (int half = 0; half < 2; half++) {
        float acc[32];
#pragma unroll
        for (int o = 0; o < 32; o++) acc[o] = sC[half * 32 + o];
        {
            const float4* wr = (const float4*)(sW0T + 0 * 64 + half * 32);
#pragma unroll
            for (int i = 0; i < 8; i++) { float4 w = wr[i];
                acc[4*i+0] = fmaf(dx, w.x, acc[4*i+0]); acc[4*i+1] = fmaf(dx, w.y, acc[4*i+1]);
                acc[4*i+2] = fmaf(dx, w.z, acc[4*i+2]); acc[4*i+3] = fmaf(dx, w.w, acc[4*i+3]); }
        }
        {
            const float4* wr = (const float4*)(sW0T + 1 * 64 + half * 32);
#pragma unroll
            for (int i = 0; i < 8; i++) { float4 w = wr[i];
                acc[4*i+0] = fmaf(dy, w.x, acc[4*i+0]); acc[4*i+1] = fmaf(dy, w.y, acc[4*i+1]);
                acc[4*i+2] = fmaf(dy, w.z, acc[4*i+2]); acc[4*i+3] = fmaf(dy, w.w, acc[4*i+3]); }
        }
        {
            const float4* wr = (const float4*)(sW0T + 2 * 64 + half * 32);
#pragma unroll
            for (int i = 0; i < 8; i++) { float4 w = wr[i];
                acc[4*i+0] = fmaf(dz, w.x, acc[4*i+0]); acc[4*i+1] = fmaf(dz, w.y, acc[4*i+1]);
                acc[4*i+2] = fmaf(dz, w.z, acc[4*i+2]); acc[4*i+3] = fmaf(dz, w.w, acc[4*i+3]); }
        }
#pragma unroll 2
        for (int c = 0; c < 64; c++) {
            float x = sF[c * 128 + t];
            const float4* wr = (const float4*)(sW0T + (3 + c) * 64 + half * 32);
#pragma unroll
            for (int i = 0; i < 8; i++) { float4 w = wr[i];
                acc[4*i+0] = fmaf(x, w.x, acc[4*i+0]); acc[4*i+1] = fmaf(x, w.y, acc[4*i+1]);
                acc[4*i+2] = fmaf(x, w.z, acc[4*i+2]); acc[4*i+3] = fmaf(x, w.w, acc[4*i+3]); }
        }
#pragma unroll
        for (int o = 0; o < 32; o++) sH[(half * 32 + o) * 128 + t] = fmaxf(acc[o], 0.f);
    }

    // ---- layer 1: 64 -> 64, two halves; h1 overwrites sF (feats no longer needed) ----
#pragma unroll 1
    for (int half = 0; half < 2; half++) {
        float acc[32];
#pragma unroll
        for (int o = 0; o < 32; o++) acc[o] = sC[64 + half * 32 + o];
#pragma unroll 2
        for (int c = 0; c < 64; c++) {
            float x = sH[c * 128 + t];
            const float4* wr = (const float4*)(sW1T + c * 64 + half * 32);
#pragma unroll
            for (int i = 0; i < 8; i++) { float4 w = wr[i];
                acc[4*i+0] = fmaf(x, w.x, acc[4*i+0]); acc[4*i+1] = fmaf(x, w.y, acc[4*i+1]);
                acc[4*i+2] = fmaf(x, w.z, acc[4*i+2]); acc[4*i+3] = fmaf(x, w.w, acc[4*i+3]); }
        }
#pragma unroll
        for (int o = 0; o < 32; o++) sF[(half * 32 + o) * 128 + t] = fmaxf(acc[o], 0.f);
    }

    // ---- layer 2: 64 -> 128, four quarters; relu + warp-max + lane0 store ----
#pragma unroll 1
    for (int quar = 0; quar < 4; quar++) {
        float acc[32];
#pragma unroll
        for (int o = 0; o < 32; o++) acc[o] = sC[128 + quar * 32 + o];
#pragma unroll 2
        for (int c = 0; c < 64; c++) {
            float x = sF[c * 128 + t];
            const float4* wr = (const float4*)(sW2T + c * 128 + quar * 32);
#pragma unroll
            for (int i = 0; i < 8; i++) { float4 w = wr[i];
                acc[4*i+0] = fmaf(x, w.x, acc[4*i+0]); acc[4*i+1] = fmaf(x, w.y, acc[4*i+1]);
                acc[4*i+2] = fmaf(x, w.z, acc[4*i+2]); acc[4*i+3] = fmaf(x, w.w, acc[4*i+3]); }
        }
#pragma unroll
        for (int o = 0; o < 32; o += 4) {
            float a0 = fmaxf(acc[o + 0], 0.f), a1 = fmaxf(acc[o + 1], 0.f);
            float a2 = fmaxf(acc[o + 2], 0.f), a3 = fmaxf(acc[o + 3], 0.f);
#pragma unroll
            for (int off = 16; off > 0; off >>= 1) {
                a0 = fmaxf(a0, __shfl_xor_sync(0xffffffffu, a0, off));
                a1 = fmaxf(a1, __shfl_xor_sync(0xffffffffu, a1, off));
                a2 = fmaxf(a2, __shfl_xor_sync(0xffffffffu, a2, off));
                a3 = fmaxf(a3, __shfl_xor_sync(0xffffffffu, a3, off));
            }
            if (lane == 0) *(float4*)(orow + quar * 32 + o) = make_float4(a0, a1, a2, a3);
        }
    }
}

// ---------------- launch ----------------
extern "C" void kernel_launch(void* const* d_in, const int* in_sizes, int n_in,
                              void* d_out, int out_size)
{
    const float* xyz  = (const float*)d_in[0];
    const float* feat = (const float*)d_in[1];
    const float* a[18];
    for (int i = 0; i < 18; i++) a[i] = (const float*)d_in[2 + i];

    float* out = (float*)d_out;
    float* out_xyz  = out;                        // (B,S,3)
    float* out_feat = out + (size_t)BB * SS * 3;  // (B,S,128)

    cudaFuncSetAttribute(fps_kernel, cudaFuncAttributeMaxDynamicSharedMemorySize, FPS_SMEM_BYTES);
    fps_kernel<<<BB, FPS_T, FPS_SMEM_BYTES>>>(xyz, out_xyz);

    bq_kernel<<<dim3(SS / BQ_T, BB), BQ_T>>>(xyz, out_xyz, out_feat);

    int mlp_smem = MLP_SMEM_FLOATS * (int)sizeof(float);
    cudaFuncSetAttribute(mlp_kernel, cudaFuncAttributeMaxDynamicSharedMemorySize, mlp_smem);
    mlp_kernel<<<BB * SS / 4, 128, mlp_smem>>>(
        xyz, feat,
        a[0], a[1], a[2], a[3], a[4], a[5],
        a[6], a[7], a[8], a[9], a[10], a[11],
        a[12], a[13], a[14], a[15], a[16], a[17],
        out_xyz, out_feat);
}

// round 9
// speedup vs baseline: 1.1898x; 1.1898x over previous
#include <cuda_runtime.h>
#include <math.h>

#define BB 8
#define NN 8192
#define SS 2048
#define KK 32
#define RAD 0.2f
#define EPSV 1e-5f

// NO __device__ globals, NO scratch buffers. Intermediate state lives in d_out:
//   out[0 .. B*S*3)  = new_xyz (fps)
//   out[B*S*3 ..]    = out_feat rows; bq stashes 32 neighbor ints at each row
//                      head, mlp reads then overwrites.

// ---------------- packed f32x2 helpers (per-lane IEEE fp32 rn — bit-identical math) ----
__device__ __forceinline__ unsigned long long pack2(float x) {
    unsigned long long r;
    asm("mov.b64 %0, {%1, %1};" : "=l"(r) : "f"(x));
    return r;
}
__device__ __forceinline__ void ffma2(unsigned long long& a, unsigned long long w, unsigned long long x) {
    asm("fma.rn.f32x2 %0, %1, %2, %0;" : "+l"(a) : "l"(w), "l"(x));
}
__device__ __forceinline__ float2 unpack2(unsigned long long a) {
    float2 f;
    asm("mov.b64 {%0, %1}, %2;" : "=f"(f.x), "=f"(f.y) : "l"(a));
    return f;
}

// ---------------- farthest point sampling: register scan + smem winner lookup ----------------
// 256 threads x 32 points in registers (full unroll, constant indices only).
// smem holds a read-only xyz copy used solely to broadcast the winner's coords
// by index at the top of each iteration -> only 2 barriers/iter, no dynamic
// register indexing, ~160 live regs vs 255 cap (no spill).
#define FPS_T 256
#define FPS_P 32
#define FPS_SMEM_BYTES (3 * NN * (int)sizeof(float))
__global__ void __launch_bounds__(FPS_T) fps_kernel(const float* __restrict__ xyz,
                                                    float* __restrict__ out_xyz)
{
    extern __shared__ float fsm[];
    float* sx = fsm;
    float* sy = fsm + NN;
    float* sz = fsm + 2 * NN;
    __shared__ float s_val[8];
    __shared__ int   s_idx[8];
    __shared__ int   s_win;

    const int b = blockIdx.x, tid = threadIdx.x;
    const float* X = xyz + (size_t)b * NN * 3;

    float px[FPS_P], py[FPS_P], pz[FPS_P], mind[FPS_P];
#pragma unroll
    for (int j = 0; j < FPS_P; j++) {
        int i = j * FPS_T + tid;
        float x = X[3 * i + 0], y = X[3 * i + 1], z = X[3 * i + 2];
        px[j] = x; py[j] = y; pz[j] = z; mind[j] = 1e10f;
        sx[i] = x; sy[i] = y; sz[i] = z;
    }
    if (tid == 0) {
        float* o = out_xyz + (size_t)b * SS * 3;
        o[0] = X[0]; o[1] = X[1]; o[2] = X[2];   // sample 0 = index 0
    }
    __syncthreads();

    const int lane = tid & 31, warp = tid >> 5;  // 8 warps
    int w = 0;
    for (int s = 1; s < SS; s++) {
        const float lx = sx[w], ly = sy[w], lz = sz[w];   // smem broadcast (read-only data)
        float best = -1.0f; int bidx = 0;
#pragma unroll
        for (int j = 0; j < FPS_P; j++) {
            float dx = __fadd_rn(px[j], -lx);
            float dy = __fadd_rn(py[j], -ly);
            float dz = __fadd_rn(pz[j], -lz);
            float d = __fadd_rn(__fadd_rn(__fmul_rn(dx, dx), __fmul_rn(dy, dy)), __fmul_rn(dz, dz));
            float m = fminf(mind[j], d);
            mind[j] = m;
            if (m > best) { best = m; bidx = j * FPS_T + tid; }  // strict >: lowest index on tie
        }
#pragma unroll
        for (int off = 16; off > 0; off >>= 1) {
            float ov = __shfl_xor_sync(0xffffffffu, best, off);
            int   oi = __shfl_xor_sync(0xffffffffu, bidx, off);
            if (ov > best || (ov == best && oi < bidx)) { best = ov; bidx = oi; }
        }
        if (lane == 0) { s_val[warp] = best; s_idx[warp] = bidx; }
        __syncthreads();
        if (warp == 0) {
            float v = (lane < 8) ? s_val[lane] : -2.0f;
            int   i = (lane < 8) ? s_idx[lane] : 0x7fffffff;
#pragma unroll
            for (int off = 4; off > 0; off >>= 1) {
                float ov = __shfl_xor_sync(0xffffffffu, v, off);
                int   oi = __shfl_xor_sync(0xffffffffu, i, off);
                if (ov > v || (ov == v && oi < i)) { v = ov; i = oi; }
            }
            if (lane == 0) s_win = i;
        }
        __syncthreads();
        w = s_win;
        if (tid == 0) {
            float* o = out_xyz + ((size_t)b * SS + s) * 3;
            o[0] = sx[w]; o[1] = sy[w]; o[2] = sz[w];
        }
    }
}

// ---------------- ball query: top-32 in SMEM; neighbor ints -> head of output row ----------------
#define BQ_T 128
#define BQ_TILE 1024
__global__ void __launch_bounds__(BQ_T) bq_kernel(const float* __restrict__ xyz,
                                                  const float* __restrict__ newxyz,
                                                  float* __restrict__ out_feat)
{
    const int b = blockIdx.y;
    const int s = blockIdx.x * BQ_T + threadIdx.x;
    const int tid = threadIdx.x;
    const float* X = xyz + (size_t)b * NN * 3;

    __shared__ float4 sp[BQ_TILE];                 // 16 KB point tile (xyz, |p|^2)
    __shared__ float  sd[KK * BQ_T];               // 16 KB keys   sd[j*BQ_T + tid]
    __shared__ int    sid[KK * BQ_T];              // 16 KB indices

#pragma unroll
    for (int j = 0; j < KK; j++) { sd[j * BQ_T + tid] = 3.4e38f; sid[j * BQ_T + tid] = 0; }

    const float qx = newxyz[((size_t)b * SS + s) * 3 + 0];
    const float qy = newxyz[((size_t)b * SS + s) * 3 + 1];
    const float qz = newxyz[((size_t)b * SS + s) * 3 + 2];
    const float a2 = __fadd_rn(__fadd_rn(__fmul_rn(qx, qx), __fmul_rn(qy, qy)), __fmul_rn(qz, qz));

    float worst = 3.4e38f;
    for (int t0 = 0; t0 < NN; t0 += BQ_TILE) {
        __syncthreads();
        for (int i = tid; i < BQ_TILE; i += BQ_T) {
            float x = X[(t0 + i) * 3 + 0];
            float y = X[(t0 + i) * 3 + 1];
            float z = X[(t0 + i) * 3 + 2];
            float b2 = __fadd_rn(__fadd_rn(__fmul_rn(x, x), __fmul_rn(y, y)), __fmul_rn(z, z));
            sp[i] = make_float4(x, y, z, b2);
        }
        __syncthreads();
#pragma unroll 4
        for (int i = 0; i < BQ_TILE; i++) {
            float4 p = sp[i];
            float ab = __fadd_rn(__fadd_rn(__fmul_rn(qx, p.x), __fmul_rn(qy, p.y)), __fmul_rn(qz, p.z));
            float key = fmaxf(__fadd_rn(__fadd_rn(a2, p.w), __fmul_rn(-2.0f, ab)), 0.0f);
            if (key < worst) {                                // strict <: stable ties by index
                int j = KK - 1;
                while (j > 0) {
                    float pj = sd[(j - 1) * BQ_T + tid];
                    if (pj <= key) break;
                    sd[j * BQ_T + tid]  = pj;
                    sid[j * BQ_T + tid] = sid[(j - 1) * BQ_T + tid];
                    --j;
                }
                sd[j * BQ_T + tid]  = key;
                sid[j * BQ_T + tid] = t0 + i;
                worst = sd[(KK - 1) * BQ_T + tid];
            }
        }
    }
    int* nbrow = (int*)(out_feat + (size_t)(b * SS + s) * 128);
#pragma unroll
    for (int j = 0; j < KK; j++) {
        float dist = __fsqrt_rn(sd[j * BQ_T + tid]);
        nbrow[j] = (dist < RAD) ? sid[j * BQ_T + tid] : 0;
    }
}

// ---------------- fused MLP: fold BN once per block, 8 query-groups, f32x2 FMA ----------------
// warp = query, lane = neighbor. Activations in smem columns [c][tid] (stride
// 128 -> own bank, same-thread only -> no syncs after the fold barrier).
// Weights [c][o] with o-pairs adjacent -> ulonglong2 loads feed fma.rn.f32x2.
#define MLP_G 8
#define MLP_SMEM_FLOATS (4288 + 4096 + 8192 + 256 + 256 + 8192 + 8192)
__global__ void __launch_bounds__(128) mlp_kernel(
    const float* __restrict__ xyz, const float* __restrict__ feat,
    const float* __restrict__ W0, const float* __restrict__ b0, const float* __restrict__ gg0,
    const float* __restrict__ be0, const float* __restrict__ m0, const float* __restrict__ v0,
    const float* __restrict__ W1, const float* __restrict__ b1, const float* __restrict__ gg1,
    const float* __restrict__ be1, const float* __restrict__ m1, const float* __restrict__ v1,
    const float* __restrict__ W2, const float* __restrict__ b2, const float* __restrict__ gg2,
    const float* __restrict__ be2, const float* __restrict__ m2, const float* __restrict__ v2,
    const float* __restrict__ newxyz, float* __restrict__ out_feat)
{
    extern __shared__ float dsm[];
    float* sW0T = dsm;                 // 4288  [c<67][o<64] folded
    float* sW1T = sW0T + 4288;         // 4096  [c][o]
    float* sW2T = sW1T + 4096;         // 8192  [c][o<128]
    float* sC   = sW2T + 8192;         // 256: C0[64] C1[64] C2[128]
    float* sS   = sC + 256;            // 256: s0[64] s1[64] s2[128]
    float* sF   = sS + 256;            // 8192  [c][tid] feats, later h1
    float* sH   = sF + 8192;           // 8192  [c][tid] h0

    const int t = threadIdx.x;
    if (t < 64) {
        float s0 = gg0[t] / sqrtf(v0[t] + EPSV);
        float s1 = gg1[t] / sqrtf(v1[t] + EPSV);
        sS[t] = s0; sS[64 + t] = s1;
        sC[t] = (b0[t] - m0[t]) * s0 + be0[t];
        sC[64 + t] = (b1[t] - m1[t]) * s1 + be1[t];
    }
    if (t < 128) {
        float s2 = gg2[t] / sqrtf(v2[t] + EPSV);
        sS[128 + t] = s2;
        sC[128 + t] = (b2[t] - m2[t]) * s2 + be2[t];
    }
    __syncthreads();
    for (int i = t; i < 67 * 64; i += 128)  { int c = i >> 6, o = i & 63;  sW0T[i] = W0[o * 67 + c] * sS[o]; }
    for (int i = t; i < 64 * 64; i += 128)  { int c = i >> 6, o = i & 63;  sW1T[i] = W1[o * 64 + c] * sS[64 + o]; }
    for (int i = t; i < 64 * 128; i += 128) { int c = i >> 7, o = i & 127; sW2T[i] = W2[o * 64 + c] * sS[128 + o]; }
    __syncthreads();

    const int warp = t >> 5, lane = t & 31;

#pragma unroll 1
    for (int g = 0; g < MLP_G; g++) {
        const int q = (blockIdx.x * MLP_G + g) * 4 + warp;
        const int b = q >> 11;
        const float nx = newxyz[(size_t)q * 3], ny = newxyz[(size_t)q * 3 + 1], nz = newxyz[(size_t)q * 3 + 2];
        float* orow = out_feat + (size_t)q * 128;

        const int nbi = ((const int*)orow)[lane];     // read before any row write
        const float* prow = xyz + ((size_t)b * NN + nbi) * 3;
        const float dx = prow[0] - nx, dy = prow[1] - ny, dz = prow[2] - nz;
        const unsigned long long dx2 = pack2(dx), dy2 = pack2(dy), dz2 = pack2(dz);
        const float* frow = feat + ((size_t)b * NN + nbi) * 64;
#pragma unroll
        for (int c = 0; c < 64; c += 4) {
            float4 v = *(const float4*)(frow + c);
            sF[(c + 0) * 128 + t] = v.x;
            sF[(c + 1) * 128 + t] = v.y;
            sF[(c + 2) * 128 + t] = v.z;
            sF[(c + 3) * 128 + t] = v.w;
        }

        // ---- layer 0: 67 -> 64, two halves of 32 outputs ----
#pragma unroll 1
        for (int half = 0; half < 2; half++) {
            unsigned long long acc2[16];
            const unsigned long long* cc = (const unsigned long long*)(sC + half * 32);
#pragma unroll
            for (int i = 0; i < 16; i++) acc2[i] = cc[i];
            {
                const ulonglong2* wr = (const ulonglong2*)(sW0T + 0 * 64 + half * 32);
#pragma unroll
                for (int i = 0; i < 8; i++) { ulonglong2 w = wr[i]; ffma2(acc2[2*i], w.x, dx2); ffma2(acc2[2*i+1], w.y, dx2); }
            }
            {
                const ulonglong2* wr = (const ulonglong2*)(sW0T + 1 * 64 + half * 32);
#pragma unroll
                for (int i = 0; i < 8; i++) { ulonglong2 w = wr[i]; ffma2(acc2[2*i], w.x, dy2); ffma2(acc2[2*i+1], w.y, dy2); }
            }
            {
                const ulonglong2* wr = (const ulonglong2*)(sW0T + 2 * 64 + half * 32);
#pragma unroll
                for (int i = 0; i < 8; i++) { ulonglong2 w = wr[i]; ffma2(acc2[2*i], w.x, dz2); ffma2(acc2[2*i+1], w.y, dz2); }
            }
#pragma unroll 2
            for (int c = 0; c < 64; c++) {
                unsigned long long x2 = pack2(sF[c * 128 + t]);
                const ulonglong2* wr = (const ulonglong2*)(sW0T + (3 + c) * 64 + half * 32);
#pragma unroll
                for (int i = 0; i < 8; i++) { ulonglong2 w = wr[i]; ffma2(acc2[2*i], w.x, x2); ffma2(acc2[2*i+1], w.y, x2); }
            }
#pragma unroll
            for (int i = 0; i < 16; i++) {
                float2 v = unpack2(acc2[i]);
                sH[(half * 32 + 2 * i + 0) * 128 + t] = fmaxf(v.x, 0.f);
                sH[(half * 32 + 2 * i + 1) * 128 + t] = fmaxf(v.y, 0.f);
            }
        }

        // ---- layer 1: 64 -> 64, two halves; h1 overwrites sF ----
#pragma unroll 1
        for (int half = 0; half < 2; half++) {
            unsigned long long acc2[16];
            const unsigned long long* cc = (const unsigned long long*)(sC + 64 + half * 32);
#pragma unroll
            for (int i = 0; i < 16; i++) acc2[i] = cc[i];
#pragma unroll 2
            for (int c = 0; c < 64; c++) {
                unsigned long long x2 = pack2(sH[c * 128 + t]);
                const ulonglong2* wr = (const ulonglong2*)(sW1T + c * 64 + half * 32);
#pragma unroll
                for (int i = 0; i < 8; i++) { ulonglong2 w = wr[i]; ffma2(acc2[2*i], w.x, x2); ffma2(acc2[2*i+1], w.y, x2); }
            }
#pragma unroll
            for (int i = 0; i < 16; i++) {
                float2 v = unpack2(acc2[i]);
                sF[(half * 32 + 2 * i + 0) * 128 + t] = fmaxf(v.x, 0.f);
                sF[(half * 32 + 2 * i + 1) * 128 + t] = fmaxf(v.y, 0.f);
            }
        }

        // ---- layer 2: 64 -> 128, four quarters; relu + warp-max + lane0 store ----
#pragma unroll 1
        for (int quar = 0; quar < 4; quar++) {
            unsigned long long acc2[16];
            const unsigned long long* cc = (const unsigned long long*)(sC + 128 + quar * 32);
#pragma unroll
            for (int i = 0; i < 16; i++) acc2[i] = cc[i];
#pragma unroll 2
            for (int c = 0; c < 64; c++) {
                unsigned long long x2 = pack2(sF[c * 128 + t]);
                const ulonglong2* wr = (const ulonglong2*)(sW2T + c * 128 + quar * 32);
#pragma unroll
                for (int i = 0; i < 8; i++) { ulonglong2 w = wr[i]; ffma2(acc2[2*i], w.x, x2); ffma2(acc2[2*i+1], w.y, x2); }
            }
#pragma unroll
            for (int i = 0; i < 16; i += 2) {
                float2 va = unpack2(acc2[i]);
                float2 vb = unpack2(acc2[i + 1]);
                float a0 = fmaxf(va.x, 0.f), a1 = fmaxf(va.y, 0.f);
                float a2 = fmaxf(vb.x, 0.f), a3 = fmaxf(vb.y, 0.f);
#pragma unroll
                for (int off = 16; off > 0; off >>= 1) {
                    a0 = fmaxf(a0, __shfl_xor_sync(0xffffffffu, a0, off));
                    a1 = fmaxf(a1, __shfl_xor_sync(0xffffffffu, a1, off));
                    a2 = fmaxf(a2, __shfl_xor_sync(0xffffffffu, a2, off));
                    a3 = fmaxf(a3, __shfl_xor_sync(0xffffffffu, a3, off));
                }
                if (lane == 0) *(float4*)(orow + quar * 32 + 2 * i) = make_float4(a0, a1, a2, a3);
            }
        }
    }
}

// ---------------- launch ----------------
extern "C" void kernel_launch(void* const* d_in, const int* in_sizes, int n_in,
                              void* d_out, int out_size)
{
    const float* xyz  = (const float*)d_in[0];
    const float* feat = (const float*)d_in[1];
    const float* a[18];
    for (int i = 0; i < 18; i++) a[i] = (const float*)d_in[2 + i];

    float* out = (float*)d_out;
    float* out_xyz  = out;                        // (B,S,3)
    float* out_feat = out + (size_t)BB * SS * 3;  // (B,S,128)

    cudaFuncSetAttribute(fps_kernel, cudaFuncAttributeMaxDynamicSharedMemorySize, FPS_SMEM_BYTES);
    fps_kernel<<<BB, FPS_T, FPS_SMEM_BYTES>>>(xyz, out_xyz);

    bq_kernel<<<dim3(SS / BQ_T, BB), BQ_T>>>(xyz, out_xyz, out_feat);

    int mlp_smem = MLP_SMEM_FLOATS * (int)sizeof(float);
    cudaFuncSetAttribute(mlp_kernel, cudaFuncAttributeMaxDynamicSharedMemorySize, mlp_smem);
    mlp_kernel<<<BB * SS / (4 * MLP_G), 128, mlp_smem>>>(
        xyz, feat,
        a[0], a[1], a[2], a[3], a[4], a[5],
        a[6], a[7], a[8], a[9], a[10], a[11],
        a[12], a[13], a[14], a[15], a[16], a[17],
        out_xyz, out_feat);
}

// round 11
// speedup vs baseline: 1.2917x; 1.0857x over previous
#include <cuda_runtime.h>
#include <math.h>

#define BB 8
#define NN 8192
#define SS 2048
#define KK 32
#define RAD 0.2f
#define EPSV 1e-5f

// NO __device__ globals, NO scratch. Intermediate state lives in d_out:
//   out[0 .. B*S*3)  = new_xyz (fps)
//   out[B*S*3 ..]    = out_feat rows; bq stashes 32 neighbor ints at each row
//                      head, mlp reads then overwrites.

// ---------------- packed f32x2 helpers (per-half IEEE fp32 rn — proven bit-exact R9) ----
__device__ __forceinline__ unsigned long long pack2(float x) {
    unsigned long long r;
    asm("mov.b64 %0, {%1, %1};" : "=l"(r) : "f"(x));
    return r;
}
__device__ __forceinline__ unsigned long long pack2v(float lo, float hi) {
    unsigned long long r;
    asm("mov.b64 %0, {%1, %2};" : "=l"(r) : "f"(lo), "f"(hi));
    return r;
}
__device__ __forceinline__ void add2(unsigned long long& o, unsigned long long a, unsigned long long b) {
    asm("add.rn.f32x2 %0, %1, %2;" : "=l"(o) : "l"(a), "l"(b));
}
__device__ __forceinline__ void mul2(unsigned long long& o, unsigned long long a, unsigned long long b) {
    asm("mul.rn.f32x2 %0, %1, %2;" : "=l"(o) : "l"(a), "l"(b));
}
__device__ __forceinline__ void ffma2(unsigned long long& a, unsigned long long w, unsigned long long x) {
    asm("fma.rn.f32x2 %0, %1, %2, %0;" : "+l"(a) : "l"(w), "l"(x));
}
__device__ __forceinline__ float2 unpack2(unsigned long long a) {
    float2 f;
    asm("mov.b64 {%0, %1}, %2;" : "=f"(f.x), "=f"(f.y) : "l"(a));
    return f;
}

// ---------------- farthest point sampling ----------------
// 512 threads, 16 pts/thread packed as 8 f32x2 pairs. Distance math via packed
// add/mul.rn.f32x2 (per-half rn, identical op order to reference). Argmax via a
// depth-5 tournament tree (left-wins-ties => lowest index) instead of a 32-deep
// serial compare chain. ~91 regs at a 128-reg cap, no dynamic reg indexing.
#define FPS_T 512
#define FPS_SMEM_BYTES (3 * NN * (int)sizeof(float))
__global__ void __launch_bounds__(FPS_T) fps_kernel(const float* __restrict__ xyz,
                                                    float* __restrict__ out_xyz)
{
    extern __shared__ float fsm[];
    float* sx = fsm;
    float* sy = fsm + NN;
    float* sz = fsm + 2 * NN;
    __shared__ float s_val[16];
    __shared__ int   s_idx[16];
    __shared__ int   s_win;

    const int b = blockIdx.x, tid = threadIdx.x;
    const float* X = xyz + (size_t)b * NN * 3;

    unsigned long long px2[8], py2[8], pz2[8];
    float mind[16];
#pragma unroll
    for (int k = 0; k < 8; k++) {
        int ilo = (2 * k) * FPS_T + tid, ihi = ilo + FPS_T;
        float xl = X[3 * ilo], yl = X[3 * ilo + 1], zl = X[3 * ilo + 2];
        float xh = X[3 * ihi], yh = X[3 * ihi + 1], zh = X[3 * ihi + 2];
        px2[k] = pack2v(xl, xh); py2[k] = pack2v(yl, yh); pz2[k] = pack2v(zl, zh);
        sx[ilo] = xl; sy[ilo] = yl; sz[ilo] = zl;
        sx[ihi] = xh; sy[ihi] = yh; sz[ihi] = zh;
        mind[2 * k] = 1e10f; mind[2 * k + 1] = 1e10f;
    }
    if (tid == 0) {
        float* o = out_xyz + (size_t)b * SS * 3;
        o[0] = X[0]; o[1] = X[1]; o[2] = X[2];   // sample 0 = index 0
    }
    __syncthreads();

    const int lane = tid & 31, warp = tid >> 5;  // 16 warps
    int w = 0;
    for (int s = 1; s < SS; s++) {
        const unsigned long long nlx = pack2(-sx[w]);
        const unsigned long long nly = pack2(-sy[w]);
        const unsigned long long nlz = pack2(-sz[w]);
#pragma unroll
        for (int k = 0; k < 8; k++) {
            unsigned long long dx, dy, dz, xx, yy, zz, s12, dd;
            add2(dx, px2[k], nlx);           // p - l  (per-half rn, == fsub)
            add2(dy, py2[k], nly);
            add2(dz, pz2[k], nlz);
            mul2(xx, dx, dx);
            mul2(yy, dy, dy);
            mul2(zz, dz, dz);
            add2(s12, xx, yy);               // (x^2+y^2)
            add2(dd, s12, zz);               // +z^2  — same order as reference
            float2 d = unpack2(dd);
            mind[2 * k]     = fminf(mind[2 * k], d.x);
            mind[2 * k + 1] = fminf(mind[2 * k + 1], d.y);
        }
        // tournament argmax over mind[16]; left wins ties -> lowest j (== first max)
        float v8[8]; int j8[8];
#pragma unroll
        for (int n = 0; n < 8; n++) {
            bool g = mind[2 * n + 1] > mind[2 * n];
            v8[n] = g ? mind[2 * n + 1] : mind[2 * n];
            j8[n] = g ? (2 * n + 1) : (2 * n);
        }
        float v4[4]; int j4[4];
#pragma unroll
        for (int n = 0; n < 4; n++) {
            bool g = v8[2 * n + 1] > v8[2 * n];
            v4[n] = g ? v8[2 * n + 1] : v8[2 * n];
            j4[n] = g ? j8[2 * n + 1] : j8[2 * n];
        }
        float v2[2]; int j2[2];
#pragma unroll
        for (int n = 0; n < 2; n++) {
            bool g = v4[2 * n + 1] > v4[2 * n];
            v2[n] = g ? v4[2 * n + 1] : v4[2 * n];
            j2[n] = g ? j4[2 * n + 1] : j4[2 * n];
        }
        bool gf = v2[1] > v2[0];
        float best = gf ? v2[1] : v2[0];
        int bidx = (gf ? j2[1] : j2[0]) * FPS_T + tid;
#pragma unroll
        for (int off = 16; off > 0; off >>= 1) {
            float ov = __shfl_xor_sync(0xffffffffu, best, off);
            int   oi = __shfl_xor_sync(0xffffffffu, bidx, off);
            if (ov > best || (ov == best && oi < bidx)) { best = ov; bidx = oi; }
        }
        if (lane == 0) { s_val[warp] = best; s_idx[warp] = bidx; }
        __syncthreads();
        if (warp == 0) {
            float v = (lane < 16) ? s_val[lane] : -2.0f;
            int   i = (lane < 16) ? s_idx[lane] : 0x7fffffff;
#pragma unroll
            for (int off = 8; off > 0; off >>= 1) {
                float ov = __shfl_xor_sync(0xffffffffu, v, off);
                int   oi = __shfl_xor_sync(0xffffffffu, i, off);
                if (ov > v || (ov == v && oi < i)) { v = ov; i = oi; }
            }
            if (lane == 0) s_win = i;
        }
        __syncthreads();
        w = s_win;
        if (tid == 0) {
            float* o = out_xyz + ((size_t)b * SS + s) * 3;
            o[0] = sx[w]; o[1] = sy[w]; o[2] = sz[w];
        }
    }
}

// ---------------- ball query: 4-way split scan + stable lexicographic merge ----------------
// Block = 32 queries x 4 splits. warp = split (candidate quarter), lane = query.
// Each (split, query) builds a stable top-32 of its 2048-range in smem columns
// (conflict-free [slot][col] layout); warp 0 then merges the 4 sorted lists per
// query by (key, idx) lexicographic order == stable argsort top-32 of the union.
#define BQ_T 128
#define BQ_CHUNK 1024
#define BQ_SMEM_FLOATS (4 * BQ_CHUNK * 4 + KK * BQ_T + KK * BQ_T)
__global__ void __launch_bounds__(BQ_T) bq_kernel(const float* __restrict__ xyz,
                                                  const float* __restrict__ newxyz,
                                                  float* __restrict__ out_feat)
{
    extern __shared__ float qsm[];
    float4* sp = (float4*)qsm;                 // [4][1024] per-warp chunk (64 KB)
    float*  sd = qsm + 4 * BQ_CHUNK * 4;       // [KK][128] keys    (16 KB)
    int*    sid = (int*)(sd + KK * BQ_T);      // [KK][128] indices (16 KB)

    const int t = threadIdx.x, lane = t & 31, warp = t >> 5;
    const int b = blockIdx.y;
    const int q = blockIdx.x * 32 + lane;
    const float* X = xyz + (size_t)b * NN * 3;

#pragma unroll
    for (int j = 0; j < KK; j++) { sd[j * BQ_T + t] = 3.4e38f; sid[j * BQ_T + t] = 0x7fffffff; }

    const float qx = newxyz[((size_t)b * SS + q) * 3 + 0];
    const float qy = newxyz[((size_t)b * SS + q) * 3 + 1];
    const float qz = newxyz[((size_t)b * SS + q) * 3 + 2];
    const float a2 = __fadd_rn(__fadd_rn(__fmul_rn(qx, qx), __fmul_rn(qy, qy)), __fmul_rn(qz, qz));

    float4* myp = sp + warp * BQ_CHUNK;
    float worst = 3.4e38f;
    const int cbase = warp * (NN / 4);
    for (int c0 = cbase; c0 < cbase + NN / 4; c0 += BQ_CHUNK) {
        __syncwarp();
        for (int i = lane; i < BQ_CHUNK; i += 32) {
            float x = X[(c0 + i) * 3 + 0];
            float y = X[(c0 + i) * 3 + 1];
            float z = X[(c0 + i) * 3 + 2];
            float b2 = __fadd_rn(__fadd_rn(__fmul_rn(x, x), __fmul_rn(y, y)), __fmul_rn(z, z));
            myp[i] = make_float4(x, y, z, b2);
        }
        __syncwarp();
#pragma unroll 4
        for (int i = 0; i < BQ_CHUNK; i++) {
            float4 p = myp[i];
            float ab = __fadd_rn(__fadd_rn(__fmul_rn(qx, p.x), __fmul_rn(qy, p.y)), __fmul_rn(qz, p.z));
            float key = fmaxf(__fadd_rn(__fadd_rn(a2, p.w), __fmul_rn(-2.0f, ab)), 0.0f);
            if (key < worst) {                 // strict <: stable ties by index
                int j = KK - 1;
                while (j > 0) {
                    float pj = sd[(j - 1) * BQ_T + t];
                    if (pj <= key) break;
                    sd[j * BQ_T + t]  = pj;
                    sid[j * BQ_T + t] = sid[(j - 1) * BQ_T + t];
                    --j;
                }
                sd[j * BQ_T + t]  = key;
                sid[j * BQ_T + t] = c0 + i;
                worst = sd[(KK - 1) * BQ_T + t];
            }
        }
    }
    __syncthreads();

    // warp 0: per-query 4-way merge of sorted lists at cols lane, lane+32, lane+64, lane+96
    if (warp == 0) {
        int h0 = 0, h1 = 0, h2 = 0, h3 = 0;
        int* nbrow = (int*)(out_feat + (size_t)(b * SS + q) * 128);
#pragma unroll 1
        for (int slot = 0; slot < KK; slot++) {
            float k0 = (h0 < KK) ? sd[h0 * BQ_T + lane]      : 3.4e38f;
            int   i0 = (h0 < KK) ? sid[h0 * BQ_T + lane]     : 0x7fffffff;
            float k1 = (h1 < KK) ? sd[h1 * BQ_T + lane + 32] : 3.4e38f;
            int   i1 = (h1 < KK) ? sid[h1 * BQ_T + lane + 32]: 0x7fffffff;
            float k2 = (h2 < KK) ? sd[h2 * BQ_T + lane + 64] : 3.4e38f;
            int   i2 = (h2 < KK) ? sid[h2 * BQ_T + lane + 64]: 0x7fffffff;
            float k3 = (h3 < KK) ? sd[h3 * BQ_T + lane + 96] : 3.4e38f;
            int   i3 = (h3 < KK) ? sid[h3 * BQ_T + lane + 96]: 0x7fffffff;
            float bk = k0; int bi = i0; int sel = 0;
            if (k1 < bk || (k1 == bk && i1 < bi)) { bk = k1; bi = i1; sel = 1; }
            if (k2 < bk || (k2 == bk && i2 < bi)) { bk = k2; bi = i2; sel = 2; }
            if (k3 < bk || (k3 == bk && i3 < bi)) { bk = k3; bi = i3; sel = 3; }
            if (sel == 0) h0++; else if (sel == 1) h1++; else if (sel == 2) h2++; else h3++;
            float dist = __fsqrt_rn(bk);
            nbrow[slot] = (dist < RAD) ? bi : 0;
        }
    }
}

// ---------------- fused MLP: fold BN once per block, 8 query-groups, f32x2 FMA ----------------
#define MLP_G 8
#define MLP_SMEM_FLOATS (4288 + 4096 + 8192 + 256 + 256 + 8192 + 8192)
__global__ void __launch_bounds__(128) mlp_kernel(
    const float* __restrict__ xyz, const float* __restrict__ feat,
    const float* __restrict__ W0, const float* __restrict__ b0, const float* __restrict__ gg0,
    const float* __restrict__ be0, const float* __restrict__ m0, const float* __restrict__ v0,
    const float* __restrict__ W1, const float* __restrict__ b1, const float* __restrict__ gg1,
    const float* __restrict__ be1, const float* __restrict__ m1, const float* __restrict__ v1,
    const float* __restrict__ W2, const float* __restrict__ b2, const float* __restrict__ gg2,
    const float* __restrict__ be2, const float* __restrict__ m2, const float* __restrict__ v2,
    const float* __restrict__ newxyz, float* __restrict__ out_feat)
{
    extern __shared__ float dsm[];
    float* sW0T = dsm;                 // 4288  [c<67][o<64] folded
    float* sW1T = sW0T + 4288;         // 4096  [c][o]
    float* sW2T = sW1T + 4096;         // 8192  [c][o<128]
    float* sC   = sW2T + 8192;         // 256: C0[64] C1[64] C2[128]
    float* sS   = sC + 256;            // 256: s0[64] s1[64] s2[128]
    float* sF   = sS + 256;            // 8192  [c][tid] feats, later h1
    float* sH   = sF + 8192;           // 8192  [c][tid] h0

    const int t = threadIdx.x;
    if (t < 64) {
        float s0 = gg0[t] / sqrtf(v0[t] + EPSV);
        float s1 = gg1[t] / sqrtf(v1[t] + EPSV);
        sS[t] = s0; sS[64 + t] = s1;
        sC[t] = (b0[t] - m0[t]) * s0 + be0[t];
        sC[64 + t] = (b1[t] - m1[t]) * s1 + be1[t];
    }
    if (t < 128) {
        float s2 = gg2[t] / sqrtf(v2[t] + EPSV);
        sS[128 + t] = s2;
        sC[128 + t] = (b2[t] - m2[t]) * s2 + be2[t];
    }
    __syncthreads();
    for (int i = t; i < 67 * 64; i += 128)  { int c = i >> 6, o = i & 63;  sW0T[i] = W0[o * 67 + c] * sS[o]; }
    for (int i = t; i < 64 * 64; i += 128)  { int c = i >> 6, o = i & 63;  sW1T[i] = W1[o * 64 + c] * sS[64 + o]; }
    for (int i = t; i < 64 * 128; i += 128) { int c = i >> 7, o = i & 127; sW2T[i] = W2[o * 64 + c] * sS[128 + o]; }
    __syncthreads();

    const int warp = t >> 5, lane = t & 31;

#pragma unroll 1
    for (int g = 0; g < MLP_G; g++) {
        const int q = (blockIdx.x * MLP_G + g) * 4 + warp;
        const int b = q >> 11;
        const float nx = newxyz[(size_t)q * 3], ny = newxyz[(size_t)q * 3 + 1], nz = newxyz[(size_t)q * 3 + 2];
        float* orow = out_feat + (size_t)q * 128;

        const int nbi = ((const int*)orow)[lane];     // read before any row write
        const float* prow = xyz + ((size_t)b * NN + nbi) * 3;
        const float dx = prow[0] - nx, dy = prow[1] - ny, dz = prow[2] - nz;
        const unsigned long long dx2 = pack2(dx), dy2 = pack2(dy), dz2 = pack2(dz);
        const float* frow = feat + ((size_t)b * NN + nbi) * 64;
#pragma unroll
        for (int c = 0; c < 64; c += 4) {
            float4 v = *(const float4*)(frow + c);
            sF[(c + 0) * 128 + t] = v.x;
            sF[(c + 1) * 128 + t] = v.y;
            sF[(c + 2) * 128 + t] = v.z;
            sF[(c + 3) * 128 + t] = v.w;
        }

        // ---- layer 0: 67 -> 64, two halves of 32 outputs ----
#pragma unroll 1
        for (int half = 0; half < 2; half++) {
            unsigned long long acc2[16];
            const unsigned long long* cc = (const unsigned long long*)(sC + half * 32);
#pragma unroll
            for (int i = 0; i < 16; i++) acc2[i] = cc[i];
            {
                const ulonglong2* wr = (const ulonglong2*)(sW0T + 0 * 64 + half * 32);
#pragma unroll
                for (int i = 0; i < 8; i++) { ulonglong2 w = wr[i]; ffma2(acc2[2*i], w.x, dx2); ffma2(acc2[2*i+1], w.y, dx2); }
            }
            {
                const ulonglong2* wr = (const ulonglong2*)(sW0T + 1 * 64 + half * 32);
#pragma unroll
                for (int i = 0; i < 8; i++) { ulonglong2 w = wr[i]; ffma2(acc2[2*i], w.x, dy2); ffma2(acc2[2*i+1], w.y, dy2); }
            }
            {
                const ulonglong2* wr = (const ulonglong2*)(sW0T + 2 * 64 + half * 32);
#pragma unroll
                for (int i = 0; i < 8; i++) { ulonglong2 w = wr[i]; ffma2(acc2[2*i], w.x, dz2); ffma2(acc2[2*i+1], w.y, dz2); }
            }
#pragma unroll 2
            for (int c = 0; c < 64; c++) {
                unsigned long long x2 = pack2(sF[c * 128 + t]);
                const ulonglong2* wr = (const ulonglong2*)(sW0T + (3 + c) * 64 + half * 32);
#pragma unroll
                for (int i = 0; i < 8; i++) { ulonglong2 w = wr[i]; ffma2(acc2[2*i], w.x, x2); ffma2(acc2[2*i+1], w.y, x2); }
            }
#pragma unroll
            for (int i = 0; i < 16; i++) {
                float2 v = unpack2(acc2[i]);
                sH[(half * 32 + 2 * i + 0) * 128 + t] = fmaxf(v.x, 0.f);
                sH[(half * 32 + 2 * i + 1) * 128 + t] = fmaxf(v.y, 0.f);
            }
        }

        // ---- layer 1: 64 -> 64, two halves; h1 overwrites sF ----
#pragma unroll 1
        for (int half = 0; half < 2; half++) {
            unsigned long long acc2[16];
            const unsigned long long* cc = (const unsigned long long*)(sC + 64 + half * 32);
#pragma unroll
            for (int i = 0; i < 16; i++) acc2[i] = cc[i];
#pragma unroll 2
            for (int c = 0; c < 64; c++) {
                unsigned long long x2 = pack2(sH[c * 128 + t]);
                const ulonglong2* wr = (const ulonglong2*)(sW1T + c * 64 + half * 32);
#pragma unroll
                for (int i = 0; i < 8; i++) { ulonglong2 w = wr[i]; ffma2(acc2[2*i], w.x, x2); ffma2(acc2[2*i+1], w.y, x2); }
            }
#pragma unroll
            for (int i = 0; i < 16; i++) {
                float2 v = unpack2(acc2[i]);
                sF[(half * 32 + 2 * i + 0) * 128 + t] = fmaxf(v.x, 0.f);
                sF[(half * 32 + 2 * i + 1) * 128 + t] = fmaxf(v.y, 0.f);
            }
        }

        // ---- layer 2: 64 -> 128, four quarters; relu + warp-max + lane0 store ----
#pragma unroll 1
        for (int quar = 0; quar < 4; quar++) {
            unsigned long long acc2[16];
            const unsigned long long* cc = (const unsigned long long*)(sC + 128 + quar * 32);
#pragma unroll
            for (int i = 0; i < 16; i++) acc2[i] = cc[i];
#pragma unroll 2
            for (int c = 0; c < 64; c++) {
                unsigned long long x2 = pack2(sF[c * 128 + t]);
                const ulonglong2* wr = (const ulonglong2*)(sW2T + c * 128 + quar * 32);
#pragma unroll
                for (int i = 0; i < 8; i++) { ulonglong2 w = wr[i]; ffma2(acc2[2*i], w.x, x2); ffma2(acc2[2*i+1], w.y, x2); }
            }
#pragma unroll
            for (int i = 0; i < 16; i += 2) {
                float2 va = unpack2(acc2[i]);
                float2 vb = unpack2(acc2[i + 1]);
                float a0 = fmaxf(va.x, 0.f), a1 = fmaxf(va.y, 0.f);
                float a2 = fmaxf(vb.x, 0.f), a3 = fmaxf(vb.y, 0.f);
#pragma unroll
                for (int off = 16; off > 0; off >>= 1) {
                    a0 = fmaxf(a0, __shfl_xor_sync(0xffffffffu, a0, off));
                    a1 = fmaxf(a1, __shfl_xor_sync(0xffffffffu, a1, off));
                    a2 = fmaxf(a2, __shfl_xor_sync(0xffffffffu, a2, off));
                    a3 = fmaxf(a3, __shfl_xor_sync(0xffffffffu, a3, off));
                }
                if (lane == 0) *(float4*)(orow + quar * 32 + 2 * i) = make_float4(a0, a1, a2, a3);
            }
        }
    }
}

// ---------------- launch ----------------
extern "C" void kernel_launch(void* const* d_in, const int* in_sizes, int n_in,
                              void* d_out, int out_size)
{
    const float* xyz  = (const float*)d_in[0];
    const float* feat = (const float*)d_in[1];
    const float* a[18];
    for (int i = 0; i < 18; i++) a[i] = (const float*)d_in[2 + i];

    float* out = (float*)d_out;
    float* out_xyz  = out;                        // (B,S,3)
    float* out_feat = out + (size_t)BB * SS * 3;  // (B,S,128)

    cudaFuncSetAttribute(fps_kernel, cudaFuncAttributeMaxDynamicSharedMemorySize, FPS_SMEM_BYTES);
    fps_kernel<<<BB, FPS_T, FPS_SMEM_BYTES>>>(xyz, out_xyz);

    int bq_smem = BQ_SMEM_FLOATS * (int)sizeof(float);
    cudaFuncSetAttribute(bq_kernel, cudaFuncAttributeMaxDynamicSharedMemorySize, bq_smem);
    bq_kernel<<<dim3(SS / 32, BB), BQ_T, bq_smem>>>(xyz, out_xyz, out_feat);

    int mlp_smem = MLP_SMEM_FLOATS * (int)sizeof(float);
    cudaFuncSetAttribute(mlp_kernel, cudaFuncAttributeMaxDynamicSharedMemorySize, mlp_smem);
    mlp_kernel<<<BB * SS / (4 * MLP_G), 128, mlp_smem>>>(
        xyz, feat,
        a[0], a[1], a[2], a[3], a[4], a[5],
        a[6], a[7], a[8], a[9], a[10], a[11],
        a[12], a[13], a[14], a[15], a[16], a[17],
        out_xyz, out_feat);
}

// round 12
// speedup vs baseline: 1.6785x; 1.2994x over previous
#include <cuda_runtime.h>
#include <math.h>

#define BB 8
#define NN 8192
#define SS 2048
#define KK 32
#define RAD 0.2f
#define EPSV 1e-5f

// NO __device__ globals, NO scratch. Intermediate state lives in d_out:
//   out[0 .. B*S*3)  = new_xyz (fps)
//   out[B*S*3 ..]    = out_feat rows; bq stashes 32 neighbor ints at each row
//                      head, mlp reads then overwrites.

// ---------------- packed f32x2 helpers (per-half IEEE fp32 rn — proven bit-exact R9) ----
__device__ __forceinline__ unsigned long long pack2(float x) {
    unsigned long long r;
    asm("mov.b64 %0, {%1, %1};" : "=l"(r) : "f"(x));
    return r;
}
__device__ __forceinline__ unsigned long long pack2v(float lo, float hi) {
    unsigned long long r;
    asm("mov.b64 %0, {%1, %2};" : "=l"(r) : "f"(lo), "f"(hi));
    return r;
}
__device__ __forceinline__ void add2(unsigned long long& o, unsigned long long a, unsigned long long b) {
    asm("add.rn.f32x2 %0, %1, %2;" : "=l"(o) : "l"(a), "l"(b));
}
__device__ __forceinline__ void mul2(unsigned long long& o, unsigned long long a, unsigned long long b) {
    asm("mul.rn.f32x2 %0, %1, %2;" : "=l"(o) : "l"(a), "l"(b));
}
__device__ __forceinline__ void ffma2(unsigned long long& a, unsigned long long w, unsigned long long x) {
    asm("fma.rn.f32x2 %0, %1, %2, %0;" : "+l"(a) : "l"(w), "l"(x));
}
__device__ __forceinline__ float2 unpack2(unsigned long long a) {
    float2 f;
    asm("mov.b64 {%0, %1}, %2;" : "=f"(f.x), "=f"(f.y) : "l"(a));
    return f;
}

// ---------------- farthest point sampling ----------------
// 512 threads, 16 pts/thread as 8 f32x2 pairs, distances via packed add/mul
// (same op order as reference). Argmax reduce rebuilt around REDUX.SYNC:
//   dist >= 0  =>  float bits are u32-monotone
//   warp:  maxbits = redux.max(bits);  idx = redux.min(tied ? idx : UINT_MAX)
//   block: partials in PARITY-double-buffered smem; ONE __syncthreads; every
//          warp redundantly reduces the 16 partials (no warp0 stage, no 2nd
//          barrier — the parity buffer removes the WAR hazard).
// Exact (max, first-index) semantics preserved at every level.
#define FPS_T 512
#define FPS_SMEM_BYTES (3 * NN * (int)sizeof(float))
__global__ void __launch_bounds__(FPS_T) fps_kernel(const float* __restrict__ xyz,
                                                    float* __restrict__ out_xyz)
{
    extern __shared__ float fsm[];
    float* sx = fsm;
    float* sy = fsm + NN;
    float* sz = fsm + 2 * NN;
    __shared__ unsigned s_vb[2][16];
    __shared__ unsigned s_wi[2][16];

    const int b = blockIdx.x, tid = threadIdx.x;
    const float* X = xyz + (size_t)b * NN * 3;

    unsigned long long px2[8], py2[8], pz2[8];
    float mind[16];
#pragma unroll
    for (int k = 0; k < 8; k++) {
        int ilo = (2 * k) * FPS_T + tid, ihi = ilo + FPS_T;
        float xl = X[3 * ilo], yl = X[3 * ilo + 1], zl = X[3 * ilo + 2];
        float xh = X[3 * ihi], yh = X[3 * ihi + 1], zh = X[3 * ihi + 2];
        px2[k] = pack2v(xl, xh); py2[k] = pack2v(yl, yh); pz2[k] = pack2v(zl, zh);
        sx[ilo] = xl; sy[ilo] = yl; sz[ilo] = zl;
        sx[ihi] = xh; sy[ihi] = yh; sz[ihi] = zh;
        mind[2 * k] = 1e10f; mind[2 * k + 1] = 1e10f;
    }
    if (tid == 0) {
        float* o = out_xyz + (size_t)b * SS * 3;
        o[0] = X[0]; o[1] = X[1]; o[2] = X[2];   // sample 0 = index 0
    }
    __syncthreads();

    const int lane = tid & 31, warp = tid >> 5;  // 16 warps
    int w = 0;
    for (int s = 1; s < SS; s++) {
        const int par = s & 1;
        const unsigned long long nlx = pack2(-sx[w]);
        const unsigned long long nly = pack2(-sy[w]);
        const unsigned long long nlz = pack2(-sz[w]);
#pragma unroll
        for (int k = 0; k < 8; k++) {
            unsigned long long dx, dy, dz, xx, yy, zz, s12, dd;
            add2(dx, px2[k], nlx);           // p - l  (per-half rn, == fsub)
            add2(dy, py2[k], nly);
            add2(dz, pz2[k], nlz);
            mul2(xx, dx, dx);
            mul2(yy, dy, dy);
            mul2(zz, dz, dz);
            add2(s12, xx, yy);               // (x^2+y^2)
            add2(dd, s12, zz);               // +z^2  — same order as reference
            float2 d = unpack2(dd);
            mind[2 * k]     = fminf(mind[2 * k], d.x);
            mind[2 * k + 1] = fminf(mind[2 * k + 1], d.y);
        }
        // tournament argmax over mind[16]; left wins ties -> lowest j (== first max)
        float v8[8]; int j8[8];
#pragma unroll
        for (int n = 0; n < 8; n++) {
            bool g = mind[2 * n + 1] > mind[2 * n];
            v8[n] = g ? mind[2 * n + 1] : mind[2 * n];
            j8[n] = g ? (2 * n + 1) : (2 * n);
        }
        float v4[4]; int j4[4];
#pragma unroll
        for (int n = 0; n < 4; n++) {
            bool g = v8[2 * n + 1] > v8[2 * n];
            v4[n] = g ? v8[2 * n + 1] : v8[2 * n];
            j4[n] = g ? j8[2 * n + 1] : j8[2 * n];
        }
        float v2[2]; int j2[2];
#pragma unroll
        for (int n = 0; n < 2; n++) {
            bool g = v4[2 * n + 1] > v4[2 * n];
            v2[n] = g ? v4[2 * n + 1] : v4[2 * n];
            j2[n] = g ? j4[2 * n + 1] : j4[2 * n];
        }
        bool gf = v2[1] > v2[0];
        float best = gf ? v2[1] : v2[0];
        unsigned bidx = (unsigned)((gf ? j2[1] : j2[0]) * FPS_T + tid);

        // warp reduce via REDUX (dist>=0 -> bits monotone); exact first-max semantics
        unsigned bb = __float_as_uint(best);
        unsigned wmax = __reduce_max_sync(0xffffffffu, bb);
        unsigned cand = (bb == wmax) ? bidx : 0xffffffffu;
        unsigned wmin = __reduce_min_sync(0xffffffffu, cand);
        if (lane == 0) { s_vb[par][warp] = wmax; s_wi[par][warp] = wmin; }
        __syncthreads();
        // every warp redundantly reduces the 16 partials — no 2nd barrier needed
        unsigned v  = (lane < 16) ? s_vb[par][lane] : 0u;
        unsigned ii = (lane < 16) ? s_wi[par][lane] : 0xffffffffu;
        unsigned gb = __reduce_max_sync(0xffffffffu, v);
        unsigned gc = (v == gb) ? ii : 0xffffffffu;
        w = (int)__reduce_min_sync(0xffffffffu, gc);

        if (tid == 0) {
            float* o = out_xyz + ((size_t)b * SS + s) * 3;
            o[0] = sx[w]; o[1] = sy[w]; o[2] = sz[w];
        }
    }
}

// ---------------- ball query: 4-way split scan + stable lexicographic merge ----------------
#define BQ_T 128
#define BQ_CHUNK 1024
#define BQ_SMEM_FLOATS (4 * BQ_CHUNK * 4 + KK * BQ_T + KK * BQ_T)
__global__ void __launch_bounds__(BQ_T) bq_kernel(const float* __restrict__ xyz,
                                                  const float* __restrict__ newxyz,
                                                  float* __restrict__ out_feat)
{
    extern __shared__ float qsm[];
    float4* sp = (float4*)qsm;                 // [4][1024] per-warp chunk (64 KB)
    float*  sd = qsm + 4 * BQ_CHUNK * 4;       // [KK][128] keys    (16 KB)
    int*    sid = (int*)(sd + KK * BQ_T);      // [KK][128] indices (16 KB)

    const int t = threadIdx.x, lane = t & 31, warp = t >> 5;
    const int b = blockIdx.y;
    const int q = blockIdx.x * 32 + lane;
    const float* X = xyz + (size_t)b * NN * 3;

#pragma unroll
    for (int j = 0; j < KK; j++) { sd[j * BQ_T + t] = 3.4e38f; sid[j * BQ_T + t] = 0x7fffffff; }

    const float qx = newxyz[((size_t)b * SS + q) * 3 + 0];
    const float qy = newxyz[((size_t)b * SS + q) * 3 + 1];
    const float qz = newxyz[((size_t)b * SS + q) * 3 + 2];
    const float a2 = __fadd_rn(__fadd_rn(__fmul_rn(qx, qx), __fmul_rn(qy, qy)), __fmul_rn(qz, qz));

    float4* myp = sp + warp * BQ_CHUNK;
    float worst = 3.4e38f;
    const int cbase = warp * (NN / 4);
    for (int c0 = cbase; c0 < cbase + NN / 4; c0 += BQ_CHUNK) {
        __syncwarp();
        for (int i = lane; i < BQ_CHUNK; i += 32) {
            float x = X[(c0 + i) * 3 + 0];
            float y = X[(c0 + i) * 3 + 1];
            float z = X[(c0 + i) * 3 + 2];
            float b2 = __fadd_rn(__fadd_rn(__fmul_rn(x, x), __fmul_rn(y, y)), __fmul_rn(z, z));
            myp[i] = make_float4(x, y, z, b2);
        }
        __syncwarp();
#pragma unroll 4
        for (int i = 0; i < BQ_CHUNK; i++) {
            float4 p = myp[i];
            float ab = __fadd_rn(__fadd_rn(__fmul_rn(qx, p.x), __fmul_rn(qy, p.y)), __fmul_rn(qz, p.z));
            float key = fmaxf(__fadd_rn(__fadd_rn(a2, p.w), __fmul_rn(-2.0f, ab)), 0.0f);
            if (key < worst) {                 // strict <: stable ties by index
                int j = KK - 1;
                while (j > 0) {
                    float pj = sd[(j - 1) * BQ_T + t];
                    if (pj <= key) break;
                    sd[j * BQ_T + t]  = pj;
                    sid[j * BQ_T + t] = sid[(j - 1) * BQ_T + t];
                    --j;
                }
                sd[j * BQ_T + t]  = key;
                sid[j * BQ_T + t] = c0 + i;
                worst = sd[(KK - 1) * BQ_T + t];
            }
        }
    }
    __syncthreads();

    // warp 0: per-query 4-way merge of sorted lists at cols lane, lane+32, lane+64, lane+96
    if (warp == 0) {
        int h0 = 0, h1 = 0, h2 = 0, h3 = 0;
        int* nbrow = (int*)(out_feat + (size_t)(b * SS + q) * 128);
#pragma unroll 1
        for (int slot = 0; slot < KK; slot++) {
            float k0 = (h0 < KK) ? sd[h0 * BQ_T + lane]      : 3.4e38f;
            int   i0 = (h0 < KK) ? sid[h0 * BQ_T + lane]     : 0x7fffffff;
            float k1 = (h1 < KK) ? sd[h1 * BQ_T + lane + 32] : 3.4e38f;
            int   i1 = (h1 < KK) ? sid[h1 * BQ_T + lane + 32]: 0x7fffffff;
            float k2 = (h2 < KK) ? sd[h2 * BQ_T + lane + 64] : 3.4e38f;
            int   i2 = (h2 < KK) ? sid[h2 * BQ_T + lane + 64]: 0x7fffffff;
            float k3 = (h3 < KK) ? sd[h3 * BQ_T + lane + 96] : 3.4e38f;
            int   i3 = (h3 < KK) ? sid[h3 * BQ_T + lane + 96]: 0x7fffffff;
            float bk = k0; int bi = i0; int sel = 0;
            if (k1 < bk || (k1 == bk && i1 < bi)) { bk = k1; bi = i1; sel = 1; }
            if (k2 < bk || (k2 == bk && i2 < bi)) { bk = k2; bi = i2; sel = 2; }
            if (k3 < bk || (k3 == bk && i3 < bi)) { bk = k3; bi = i3; sel = 3; }
            if (sel == 0) h0++; else if (sel == 1) h1++; else if (sel == 2) h2++; else h3++;
            float dist = __fsqrt_rn(bk);
            nbrow[slot] = (dist < RAD) ? bi : 0;
        }
    }
}

// ---------------- fused MLP: 256 threads (8 warps = 8 queries/pass), f32x2 FMA ----------------
// 2 warps/SMSP for latency hiding; weight fold amortized over 64 queries/block.
// Activations in smem columns [c][256] (stride 256 -> own bank, same-thread only).
#define MLP_T 256
#define MLP_G 8
#define MLP_SMEM_FLOATS (4288 + 4096 + 8192 + 256 + 256 + 16384 + 16384)
__global__ void __launch_bounds__(MLP_T) mlp_kernel(
    const float* __restrict__ xyz, const float* __restrict__ feat,
    const float* __restrict__ W0, const float* __restrict__ b0, const float* __restrict__ gg0,
    const float* __restrict__ be0, const float* __restrict__ m0, const float* __restrict__ v0,
    const float* __restrict__ W1, const float* __restrict__ b1, const float* __restrict__ gg1,
    const float* __restrict__ be1, const float* __restrict__ m1, const float* __restrict__ v1,
    const float* __restrict__ W2, const float* __restrict__ b2, const float* __restrict__ gg2,
    const float* __restrict__ be2, const float* __restrict__ m2, const float* __restrict__ v2,
    const float* __restrict__ newxyz, float* __restrict__ out_feat)
{
    extern __shared__ float dsm[];
    float* sW0T = dsm;                 // 4288  [c<67][o<64] folded
    float* sW1T = sW0T + 4288;         // 4096  [c][o]
    float* sW2T = sW1T + 4096;         // 8192  [c][o<128]
    float* sC   = sW2T + 8192;         // 256: C0[64] C1[64] C2[128]
    float* sS   = sC + 256;            // 256: s0[64] s1[64] s2[128]
    float* sF   = sS + 256;            // 16384 [c][t] feats, later h1
    float* sH   = sF + 16384;          // 16384 [c][t] h0

    const int t = threadIdx.x;
    if (t < 64) {
        float s0 = gg0[t] / sqrtf(v0[t] + EPSV);
        float s1 = gg1[t] / sqrtf(v1[t] + EPSV);
        sS[t] = s0; sS[64 + t] = s1;
        sC[t] = (b0[t] - m0[t]) * s0 + be0[t];
        sC[64 + t] = (b1[t] - m1[t]) * s1 + be1[t];
    }
    if (t < 128) {
        float s2 = gg2[t] / sqrtf(v2[t] + EPSV);
        sS[128 + t] = s2;
        sC[128 + t] = (b2[t] - m2[t]) * s2 + be2[t];
    }
    __syncthreads();
    for (int i = t; i < 67 * 64; i += MLP_T)  { int c = i >> 6, o = i & 63;  sW0T[i] = W0[o * 67 + c] * sS[o]; }
    for (int i = t; i < 64 * 64; i += MLP_T)  { int c = i >> 6, o = i & 63;  sW1T[i] = W1[o * 64 + c] * sS[64 + o]; }
    for (int i = t; i < 64 * 128; i += MLP_T) { int c = i >> 7, o = i & 127; sW2T[i] = W2[o * 64 + c] * sS[128 + o]; }
    __syncthreads();

    const int warp = t >> 5, lane = t & 31;   // 8 warps = 8 queries per pass

#pragma unroll 1
    for (int g = 0; g < MLP_G; g++) {
        const int q = (blockIdx.x * MLP_G + g) * 8 + warp;
        const int b = q >> 11;
        const float nx = newxyz[(size_t)q * 3], ny = newxyz[(size_t)q * 3 + 1], nz = newxyz[(size_t)q * 3 + 2];
        float* orow = out_feat + (size_t)q * 128;

        const int nbi = ((const int*)orow)[lane];     // read before any row write
        const float* prow = xyz + ((size_t)b * NN + nbi) * 3;
        const float dx = prow[0] - nx, dy = prow[1] - ny, dz = prow[2] - nz;
        const unsigned long long dx2 = pack2(dx), dy2 = pack2(dy), dz2 = pack2(dz);
        const float* frow = feat + ((size_t)b * NN + nbi) * 64;
#pragma unroll
        for (int c = 0; c < 64; c += 4) {
            float4 v = *(const float4*)(frow + c);
            sF[(c + 0) * MLP_T + t] = v.x;
            sF[(c + 1) * MLP_T + t] = v.y;
            sF[(c + 2) * MLP_T + t] = v.z;
            sF[(c + 3) * MLP_T + t] = v.w;
        }

        // ---- layer 0: 67 -> 64, two halves of 32 outputs ----
#pragma unroll 1
        for (int half = 0; half < 2; half++) {
            unsigned long long acc2[16];
            const unsigned long long* cc = (const unsigned long long*)(sC + half * 32);
#pragma unroll
            for (int i = 0; i < 16; i++) acc2[i] = cc[i];
            {
                const ulonglong2* wr = (const ulonglong2*)(sW0T + 0 * 64 + half * 32);
#pragma unroll
                for (int i = 0; i < 8; i++) { ulonglong2 w = wr[i]; ffma2(acc2[2*i], w.x, dx2); ffma2(acc2[2*i+1], w.y, dx2); }
            }
            {
                const ulonglong2* wr = (const ulonglong2*)(sW0T + 1 * 64 + half * 32);
#pragma unroll
                for (int i = 0; i < 8; i++) { ulonglong2 w = wr[i]; ffma2(acc2[2*i], w.x, dy2); ffma2(acc2[2*i+1], w.y, dy2); }
            }
            {
                const ulonglong2* wr = (const ulonglong2*)(sW0T + 2 * 64 + half * 32);
#pragma unroll
                for (int i = 0; i < 8; i++) { ulonglong2 w = wr[i]; ffma2(acc2[2*i], w.x, dz2); ffma2(acc2[2*i+1], w.y, dz2); }
            }
#pragma unroll 2
            for (int c = 0; c < 64; c++) {
                unsigned long long x2 = pack2(sF[c * MLP_T + t]);
                const ulonglong2* wr = (const ulonglong2*)(sW0T + (3 + c) * 64 + half * 32);
#pragma unroll
                for (int i = 0; i < 8; i++) { ulonglong2 w = wr[i]; ffma2(acc2[2*i], w.x, x2); ffma2(acc2[2*i+1], w.y, x2); }
            }
#pragma unroll
            for (int i = 0; i < 16; i++) {
                float2 v = unpack2(acc2[i]);
                sH[(half * 32 + 2 * i + 0) * MLP_T + t] = fmaxf(v.x, 0.f);
                sH[(half * 32 + 2 * i + 1) * MLP_T + t] = fmaxf(v.y, 0.f);
            }
        }

        // ---- layer 1: 64 -> 64, two halves; h1 overwrites sF ----
#pragma unroll 1
        for (int half = 0; half < 2; half++) {
            unsigned long long acc2[16];
            const unsigned long long* cc = (const unsigned long long*)(sC + 64 + half * 32);
#pragma unroll
            for (int i = 0; i < 16; i++) acc2[i] = cc[i];
#pragma unroll 2
            for (int c = 0; c < 64; c++) {
                unsigned long long x2 = pack2(sH[c * MLP_T + t]);
                const ulonglong2* wr = (const ulonglong2*)(sW1T + c * 64 + half * 32);
#pragma unroll
                for (int i = 0; i < 8; i++) { ulonglong2 w = wr[i]; ffma2(acc2[2*i], w.x, x2); ffma2(acc2[2*i+1], w.y, x2); }
            }
#pragma unroll
            for (int i = 0; i < 16; i++) {
                float2 v = unpack2(acc2[i]);
                sF[(half * 32 + 2 * i + 0) * MLP_T + t] = fmaxf(v.x, 0.f);
                sF[(half * 32 + 2 * i + 1) * MLP_T + t] = fmaxf(v.y, 0.f);
            }
        }

        // ---- layer 2: 64 -> 128, four quarters; relu + warp-max + lane0 store ----
#pragma unroll 1
        for (int quar = 0; quar < 4; quar++) {
            unsigned long long acc2[16];
            const unsigned long long* cc = (const unsigned long long*)(sC + 128 + quar * 32);
#pragma unroll
            for (int i = 0; i < 16; i++) acc2[i] = cc[i];
#pragma unroll 2
            for (int c = 0; c < 64; c++) {
                unsigned long long x2 = pack2(sF[c * MLP_T + t]);
                const ulonglong2* wr = (const ulonglong2*)(sW2T + c * 128 + quar * 32);
#pragma unroll
                for (int i = 0; i < 8; i++) { ulonglong2 w = wr[i]; ffma2(acc2[2*i], w.x, x2); ffma2(acc2[2*i+1], w.y, x2); }
            }
#pragma unroll
            for (int i = 0; i < 16; i += 2) {
                float2 va = unpack2(acc2[i]);
                float2 vb = unpack2(acc2[i + 1]);
                float a0 = fmaxf(va.x, 0.f), a1 = fmaxf(va.y, 0.f);
                float a2 = fmaxf(vb.x, 0.f), a3 = fmaxf(vb.y, 0.f);
#pragma unroll
                for (int off = 16; off > 0; off >>= 1) {
                    a0 = fmaxf(a0, __shfl_xor_sync(0xffffffffu, a0, off));
                    a1 = fmaxf(a1, __shfl_xor_sync(0xffffffffu, a1, off));
                    a2 = fmaxf(a2, __shfl_xor_sync(0xffffffffu, a2, off));
                    a3 = fmaxf(a3, __shfl_xor_sync(0xffffffffu, a3, off));
                }
                if (lane == 0) *(float4*)(orow + quar * 32 + 2 * i) = make_float4(a0, a1, a2, a3);
            }
        }
    }
}

// ---------------- launch ----------------
extern "C" void kernel_launch(void* const* d_in, const int* in_sizes, int n_in,
                              void* d_out, int out_size)
{
    const float* xyz  = (const float*)d_in[0];
    const float* feat = (const float*)d_in[1];
    const float* a[18];
    for (int i = 0; i < 18; i++) a[i] = (const float*)d_in[2 + i];

    float* out = (float*)d_out;
    float* out_xyz  = out;                        // (B,S,3)
    float* out_feat = out + (size_t)BB * SS * 3;  // (B,S,128)

    cudaFuncSetAttribute(fps_kernel, cudaFuncAttributeMaxDynamicSharedMemorySize, FPS_SMEM_BYTES);
    fps_kernel<<<BB, FPS_T, FPS_SMEM_BYTES>>>(xyz, out_xyz);

    int bq_smem = BQ_SMEM_FLOATS * (int)sizeof(float);
    cudaFuncSetAttribute(bq_kernel, cudaFuncAttributeMaxDynamicSharedMemorySize, bq_smem);
    bq_kernel<<<dim3(SS / 32, BB), BQ_T, bq_smem>>>(xyz, out_xyz, out_feat);

    int mlp_smem = MLP_SMEM_FLOATS * (int)sizeof(float);
    cudaFuncSetAttribute(mlp_kernel, cudaFuncAttributeMaxDynamicSharedMemorySize, mlp_smem);
    mlp_kernel<<<BB * SS / (8 * MLP_G), MLP_T, mlp_smem>>>(
        xyz, feat,
        a[0], a[1], a[2], a[3], a[4], a[5],
        a[6], a[7], a[8], a[9], a[10], a[11],
        a[12], a[13], a[14], a[15], a[16], a[17],
        out_xyz, out_feat);
}

// round 13
// speedup vs baseline: 2.9268x; 1.7437x over previous
#include <cuda_runtime.h>
#include <math.h>

#define BB 8
#define NN 8192
#define SS 2048
#define KK 32
#define RAD 0.2f
#define EPSV 1e-5f

// NO __device__ globals, NO scratch. Intermediate state lives in d_out:
//   out[0 .. B*S*3)  = new_xyz (fps)
//   out[B*S*3 ..]    = out_feat rows; bq stashes 32 neighbor ints at each row
//                      head, mlp reads then overwrites.

// ---------------- packed f32x2 helpers (per-half IEEE fp32 rn — proven bit-exact R9) ----
__device__ __forceinline__ unsigned long long pack2(float x) {
    unsigned long long r;
    asm("mov.b64 %0, {%1, %1};" : "=l"(r) : "f"(x));
    return r;
}
__device__ __forceinline__ unsigned long long pack2v(float lo, float hi) {
    unsigned long long r;
    asm("mov.b64 %0, {%1, %2};" : "=l"(r) : "f"(lo), "f"(hi));
    return r;
}
__device__ __forceinline__ void add2(unsigned long long& o, unsigned long long a, unsigned long long b) {
    asm("add.rn.f32x2 %0, %1, %2;" : "=l"(o) : "l"(a), "l"(b));
}
__device__ __forceinline__ void mul2(unsigned long long& o, unsigned long long a, unsigned long long b) {
    asm("mul.rn.f32x2 %0, %1, %2;" : "=l"(o) : "l"(a), "l"(b));
}
__device__ __forceinline__ void ffma2(unsigned long long& a, unsigned long long w, unsigned long long x) {
    asm("fma.rn.f32x2 %0, %1, %2, %0;" : "+l"(a) : "l"(w), "l"(x));
}
__device__ __forceinline__ float2 unpack2(unsigned long long a) {
    float2 f;
    asm("mov.b64 {%0, %1}, %2;" : "=f"(f.x), "=f"(f.y) : "l"(a));
    return f;
}

// ---------------- farthest point sampling (unchanged from R12) ----------------
#define FPS_T 512
#define FPS_SMEM_BYTES (3 * NN * (int)sizeof(float))
__global__ void __launch_bounds__(FPS_T) fps_kernel(const float* __restrict__ xyz,
                                                    float* __restrict__ out_xyz)
{
    extern __shared__ float fsm[];
    float* sx = fsm;
    float* sy = fsm + NN;
    float* sz = fsm + 2 * NN;
    __shared__ unsigned s_vb[2][16];
    __shared__ unsigned s_wi[2][16];

    const int b = blockIdx.x, tid = threadIdx.x;
    const float* X = xyz + (size_t)b * NN * 3;

    unsigned long long px2[8], py2[8], pz2[8];
    float mind[16];
#pragma unroll
    for (int k = 0; k < 8; k++) {
        int ilo = (2 * k) * FPS_T + tid, ihi = ilo + FPS_T;
        float xl = X[3 * ilo], yl = X[3 * ilo + 1], zl = X[3 * ilo + 2];
        float xh = X[3 * ihi], yh = X[3 * ihi + 1], zh = X[3 * ihi + 2];
        px2[k] = pack2v(xl, xh); py2[k] = pack2v(yl, yh); pz2[k] = pack2v(zl, zh);
        sx[ilo] = xl; sy[ilo] = yl; sz[ilo] = zl;
        sx[ihi] = xh; sy[ihi] = yh; sz[ihi] = zh;
        mind[2 * k] = 1e10f; mind[2 * k + 1] = 1e10f;
    }
    if (tid == 0) {
        float* o = out_xyz + (size_t)b * SS * 3;
        o[0] = X[0]; o[1] = X[1]; o[2] = X[2];   // sample 0 = index 0
    }
    __syncthreads();

    const int lane = tid & 31, warp = tid >> 5;  // 16 warps
    int w = 0;
    for (int s = 1; s < SS; s++) {
        const int par = s & 1;
        const unsigned long long nlx = pack2(-sx[w]);
        const unsigned long long nly = pack2(-sy[w]);
        const unsigned long long nlz = pack2(-sz[w]);
#pragma unroll
        for (int k = 0; k < 8; k++) {
            unsigned long long dx, dy, dz, xx, yy, zz, s12, dd;
            add2(dx, px2[k], nlx);
            add2(dy, py2[k], nly);
            add2(dz, pz2[k], nlz);
            mul2(xx, dx, dx);
            mul2(yy, dy, dy);
            mul2(zz, dz, dz);
            add2(s12, xx, yy);
            add2(dd, s12, zz);
            float2 d = unpack2(dd);
            mind[2 * k]     = fminf(mind[2 * k], d.x);
            mind[2 * k + 1] = fminf(mind[2 * k + 1], d.y);
        }
        float v8[8]; int j8[8];
#pragma unroll
        for (int n = 0; n < 8; n++) {
            bool g = mind[2 * n + 1] > mind[2 * n];
            v8[n] = g ? mind[2 * n + 1] : mind[2 * n];
            j8[n] = g ? (2 * n + 1) : (2 * n);
        }
        float v4[4]; int j4[4];
#pragma unroll
        for (int n = 0; n < 4; n++) {
            bool g = v8[2 * n + 1] > v8[2 * n];
            v4[n] = g ? v8[2 * n + 1] : v8[2 * n];
            j4[n] = g ? j8[2 * n + 1] : j8[2 * n];
        }
        float v2[2]; int j2[2];
#pragma unroll
        for (int n = 0; n < 2; n++) {
            bool g = v4[2 * n + 1] > v4[2 * n];
            v2[n] = g ? v4[2 * n + 1] : v4[2 * n];
            j2[n] = g ? j4[2 * n + 1] : j4[2 * n];
        }
        bool gf = v2[1] > v2[0];
        float best = gf ? v2[1] : v2[0];
        unsigned bidx = (unsigned)((gf ? j2[1] : j2[0]) * FPS_T + tid);

        unsigned bb = __float_as_uint(best);
        unsigned wmax = __reduce_max_sync(0xffffffffu, bb);
        unsigned cand = (bb == wmax) ? bidx : 0xffffffffu;
        unsigned wmin = __reduce_min_sync(0xffffffffu, cand);
        if (lane == 0) { s_vb[par][warp] = wmax; s_wi[par][warp] = wmin; }
        __syncthreads();
        unsigned v  = (lane < 16) ? s_vb[par][lane] : 0u;
        unsigned ii = (lane < 16) ? s_wi[par][lane] : 0xffffffffu;
        unsigned gb = __reduce_max_sync(0xffffffffu, v);
        unsigned gc = (v == gb) ? ii : 0xffffffffu;
        w = (int)__reduce_min_sync(0xffffffffu, gc);

        if (tid == 0) {
            float* o = out_xyz + ((size_t)b * SS + s) * 3;
            o[0] = sx[w]; o[1] = sy[w]; o[2] = sz[w];
        }
    }
}

// ---------------- ball query v2: warp-per-query, register-resident sorted top-32 ----------------
// Lane j holds the j-th smallest (key, idx). Per 32-candidate chunk: each lane
// computes its candidate's key (exact reference formula), ballot the ones that
// beat the current worst, insert them serially in ascending index order via a
// warp-synchronous shfl_up shift. Strictly-greater ballot => new entry lands
// AFTER equal keys => exactly stable-argsort-top-32 (ties by index). No smem,
// no divergence, no dependent-LDS chains.
#define BQ2_T 256
__global__ void __launch_bounds__(BQ2_T) bq_kernel(const float* __restrict__ xyz,
                                                   const float* __restrict__ newxyz,
                                                   float* __restrict__ out_feat)
{
    const int t = threadIdx.x, lane = t & 31, warp = t >> 5;
    const int q = blockIdx.x * 8 + warp;          // 0 .. B*S-1
    const int b = q >> 11;
    const float* X = xyz + (size_t)b * NN * 3;

    const float qx = newxyz[(size_t)q * 3 + 0];
    const float qy = newxyz[(size_t)q * 3 + 1];
    const float qz = newxyz[(size_t)q * 3 + 2];
    const float a2 = __fadd_rn(__fadd_rn(__fmul_rn(qx, qx), __fmul_rn(qy, qy)), __fmul_rn(qz, qz));

    float myk = 3.4e38f;          // lane j = j-th smallest key
    int   myi = 0x7fffffff;
    float worst = 3.4e38f;        // == lane 31's key, kept warp-uniform

#pragma unroll 1
    for (int c0 = 0; c0 < NN; c0 += 32) {
        const int ci = c0 + lane;
        const float x = X[ci * 3 + 0];
        const float y = X[ci * 3 + 1];
        const float z = X[ci * 3 + 2];
        const float b2 = __fadd_rn(__fadd_rn(__fmul_rn(x, x), __fmul_rn(y, y)), __fmul_rn(z, z));
        const float ab = __fadd_rn(__fadd_rn(__fmul_rn(qx, x), __fmul_rn(qy, y)), __fmul_rn(qz, z));
        const float key = fmaxf(__fadd_rn(__fadd_rn(a2, b2), __fmul_rn(-2.0f, ab)), 0.0f);

        unsigned pass = __ballot_sync(0xffffffffu, key < worst);
        while (pass) {
            const int src = __ffs(pass) - 1;      // ascending lane = ascending index
            pass &= pass - 1;
            const float nk = __shfl_sync(0xffffffffu, key, src);
            if (nk < worst) {                     // worst may have tightened
                // suffix mask of strictly-greater entries (list sorted ascending)
                unsigned gt = __ballot_sync(0xffffffffu, myk > nk);
                float upk = __shfl_up_sync(0xffffffffu, myk, 1);
                int   upi = __shfl_up_sync(0xffffffffu, myi, 1);
                int pos = __ffs(gt) - 1;          // gt != 0 since lane31 (worst) > nk
                if (lane > pos)       { myk = upk; myi = upi; }
                else if (lane == pos) { myk = nk;  myi = c0 + src; }
                worst = __shfl_sync(0xffffffffu, myk, 31);
            }
        }
    }

    int* nbrow = (int*)(out_feat + (size_t)q * 128);
    float dist = __fsqrt_rn(myk);
    nbrow[lane] = (dist < RAD) ? myi : 0;         // -1 sentinel clamps to 0 anyway
}

// ---------------- fused MLP (unchanged from R12): 256 threads, f32x2 FMA ----------------
#define MLP_T 256
#define MLP_G 8
#define MLP_SMEM_FLOATS (4288 + 4096 + 8192 + 256 + 256 + 16384 + 16384)
__global__ void __launch_bounds__(MLP_T) mlp_kernel(
    const float* __restrict__ xyz, const float* __restrict__ feat,
    const float* __restrict__ W0, const float* __restrict__ b0, const float* __restrict__ gg0,
    const float* __restrict__ be0, const float* __restrict__ m0, const float* __restrict__ v0,
    const float* __restrict__ W1, const float* __restrict__ b1, const float* __restrict__ gg1,
    const float* __restrict__ be1, const float* __restrict__ m1, const float* __restrict__ v1,
    const float* __restrict__ W2, const float* __restrict__ b2, const float* __restrict__ gg2,
    const float* __restrict__ be2, const float* __restrict__ m2, const float* __restrict__ v2,
    const float* __restrict__ newxyz, float* __restrict__ out_feat)
{
    extern __shared__ float dsm[];
    float* sW0T = dsm;                 // 4288  [c<67][o<64] folded
    float* sW1T = sW0T + 4288;         // 4096  [c][o]
    float* sW2T = sW1T + 4096;         // 8192  [c][o<128]
    float* sC   = sW2T + 8192;         // 256: C0[64] C1[64] C2[128]
    float* sS   = sC + 256;            // 256: s0[64] s1[64] s2[128]
    float* sF   = sS + 256;            // 16384 [c][t] feats, later h1
    float* sH   = sF + 16384;          // 16384 [c][t] h0

    const int t = threadIdx.x;
    if (t < 64) {
        float s0 = gg0[t] / sqrtf(v0[t] + EPSV);
        float s1 = gg1[t] / sqrtf(v1[t] + EPSV);
        sS[t] = s0; sS[64 + t] = s1;
        sC[t] = (b0[t] - m0[t]) * s0 + be0[t];
        sC[64 + t] = (b1[t] - m1[t]) * s1 + be1[t];
    }
    if (t < 128) {
        float s2 = gg2[t] / sqrtf(v2[t] + EPSV);
        sS[128 + t] = s2;
        sC[128 + t] = (b2[t] - m2[t]) * s2 + be2[t];
    }
    __syncthreads();
    for (int i = t; i < 67 * 64; i += MLP_T)  { int c = i >> 6, o = i & 63;  sW0T[i] = W0[o * 67 + c] * sS[o]; }
    for (int i = t; i < 64 * 64; i += MLP_T)  { int c = i >> 6, o = i & 63;  sW1T[i] = W1[o * 64 + c] * sS[64 + o]; }
    for (int i = t; i < 64 * 128; i += MLP_T) { int c = i >> 7, o = i & 127; sW2T[i] = W2[o * 64 + c] * sS[128 + o]; }
    __syncthreads();

    const int warp = t >> 5, lane = t & 31;   // 8 warps = 8 queries per pass

#pragma unroll 1
    for (int g = 0; g < MLP_G; g++) {
        const int q = (blockIdx.x * MLP_G + g) * 8 + warp;
        const int b = q >> 11;
        const float nx = newxyz[(size_t)q * 3], ny = newxyz[(size_t)q * 3 + 1], nz = newxyz[(size_t)q * 3 + 2];
        float* orow = out_feat + (size_t)q * 128;

        const int nbi = ((const int*)orow)[lane];     // read before any row write
        const float* prow = xyz + ((size_t)b * NN + nbi) * 3;
        const float dx = prow[0] - nx, dy = prow[1] - ny, dz = prow[2] - nz;
        const unsigned long long dx2 = pack2(dx), dy2 = pack2(dy), dz2 = pack2(dz);
        const float* frow = feat + ((size_t)b * NN + nbi) * 64;
#pragma unroll
        for (int c = 0; c < 64; c += 4) {
            float4 v = *(const float4*)(frow + c);
            sF[(c + 0) * MLP_T + t] = v.x;
            sF[(c + 1) * MLP_T + t] = v.y;
            sF[(c + 2) * MLP_T + t] = v.z;
            sF[(c + 3) * MLP_T + t] = v.w;
        }

        // ---- layer 0: 67 -> 64, two halves of 32 outputs ----
#pragma unroll 1
        for (int half = 0; half < 2; half++) {
            unsigned long long acc2[16];
            const unsigned long long* cc = (const unsigned long long*)(sC + half * 32);
#pragma unroll
            for (int i = 0; i < 16; i++) acc2[i] = cc[i];
            {
                const ulonglong2* wr = (const ulonglong2*)(sW0T + 0 * 64 + half * 32);
#pragma unroll
                for (int i = 0; i < 8; i++) { ulonglong2 w = wr[i]; ffma2(acc2[2*i], w.x, dx2); ffma2(acc2[2*i+1], w.y, dx2); }
            }
            {
                const ulonglong2* wr = (const ulonglong2*)(sW0T + 1 * 64 + half * 32);
#pragma unroll
                for (int i = 0; i < 8; i++) { ulonglong2 w = wr[i]; ffma2(acc2[2*i], w.x, dy2); ffma2(acc2[2*i+1], w.y, dy2); }
            }
            {
                const ulonglong2* wr = (const ulonglong2*)(sW0T + 2 * 64 + half * 32);
#pragma unroll
                for (int i = 0; i < 8; i++) { ulonglong2 w = wr[i]; ffma2(acc2[2*i], w.x, dz2); ffma2(acc2[2*i+1], w.y, dz2); }
            }
#pragma unroll 2
            for (int c = 0; c < 64; c++) {
                unsigned long long x2 = pack2(sF[c * MLP_T + t]);
                const ulonglong2* wr = (const ulonglong2*)(sW0T + (3 + c) * 64 + half * 32);
#pragma unroll
                for (int i = 0; i < 8; i++) { ulonglong2 w = wr[i]; ffma2(acc2[2*i], w.x, x2); ffma2(acc2[2*i+1], w.y, x2); }
            }
#pragma unroll
            for (int i = 0; i < 16; i++) {
                float2 v = unpack2(acc2[i]);
                sH[(half * 32 + 2 * i + 0) * MLP_T + t] = fmaxf(v.x, 0.f);
                sH[(half * 32 + 2 * i + 1) * MLP_T + t] = fmaxf(v.y, 0.f);
            }
        }

        // ---- layer 1: 64 -> 64, two halves; h1 overwrites sF ----
#pragma unroll 1
        for (int half = 0; half < 2; half++) {
            unsigned long long acc2[16];
            const unsigned long long* cc = (const unsigned long long*)(sC + 64 + half * 32);
#pragma unroll
            for (int i = 0; i < 16; i++) acc2[i] = cc[i];
#pragma unroll 2
            for (int c = 0; c < 64; c++) {
                unsigned long long x2 = pack2(sH[c * MLP_T + t]);
                const ulonglong2* wr = (const ulonglong2*)(sW1T + c * 64 + half * 32);
#pragma unroll
                for (int i = 0; i < 8; i++) { ulonglong2 w = wr[i]; ffma2(acc2[2*i], w.x, x2); ffma2(acc2[2*i+1], w.y, x2); }
            }
#pragma unroll
            for (int i = 0; i < 16; i++) {
                float2 v = unpack2(acc2[i]);
                sF[(half * 32 + 2 * i + 0) * MLP_T + t] = fmaxf(v.x, 0.f);
                sF[(half * 32 + 2 * i + 1) * MLP_T + t] = fmaxf(v.y, 0.f);
            }
        }

        // ---- layer 2: 64 -> 128, four quarters; relu + warp-max + lane0 store ----
#pragma unroll 1
        for (int quar = 0; quar < 4; quar++) {
            unsigned long long acc2[16];
            const unsigned long long* cc = (const unsigned long long*)(sC + 128 + quar * 32);
#pragma unroll
            for (int i = 0; i < 16; i++) acc2[i] = cc[i];
#pragma unroll 2
            for (int c = 0; c < 64; c++) {
                unsigned long long x2 = pack2(sF[c * MLP_T + t]);
                const ulonglong2* wr = (const ulonglong2*)(sW2T + c * 128 + quar * 32);
#pragma unroll
                for (int i = 0; i < 8; i++) { ulonglong2 w = wr[i]; ffma2(acc2[2*i], w.x, x2); ffma2(acc2[2*i+1], w.y, x2); }
            }
#pragma unroll
            for (int i = 0; i < 16; i += 2) {
                float2 va = unpack2(acc2[i]);
                float2 vb = unpack2(acc2[i + 1]);
                float a0 = fmaxf(va.x, 0.f), a1 = fmaxf(va.y, 0.f);
                float a2 = fmaxf(vb.x, 0.f), a3 = fmaxf(vb.y, 0.f);
#pragma unroll
                for (int off = 16; off > 0; off >>= 1) {
                    a0 = fmaxf(a0, __shfl_xor_sync(0xffffffffu, a0, off));
                    a1 = fmaxf(a1, __shfl_xor_sync(0xffffffffu, a1, off));
                    a2 = fmaxf(a2, __shfl_xor_sync(0xffffffffu, a2, off));
                    a3 = fmaxf(a3, __shfl_xor_sync(0xffffffffu, a3, off));
                }
                if (lane == 0) *(float4*)(orow + quar * 32 + 2 * i) = make_float4(a0, a1, a2, a3);
            }
        }
    }
}

// ---------------- launch ----------------
extern "C" void kernel_launch(void* const* d_in, const int* in_sizes, int n_in,
                              void* d_out, int out_size)
{
    const float* xyz  = (const float*)d_in[0];
    const float* feat = (const float*)d_in[1];
    const float* a[18];
    for (int i = 0; i < 18; i++) a[i] = (const float*)d_in[2 + i];

    float* out = (float*)d_out;
    float* out_xyz  = out;                        // (B,S,3)
    float* out_feat = out + (size_t)BB * SS * 3;  // (B,S,128)

    cudaFuncSetAttribute(fps_kernel, cudaFuncAttributeMaxDynamicSharedMemorySize, FPS_SMEM_BYTES);
    fps_kernel<<<BB, FPS_T, FPS_SMEM_BYTES>>>(xyz, out_xyz);

    bq_kernel<<<BB * SS / 8, BQ2_T>>>(xyz, out_xyz, out_feat);

    int mlp_smem = MLP_SMEM_FLOATS * (int)sizeof(float);
    cudaFuncSetAttribute(mlp_kernel, cudaFuncAttributeMaxDynamicSharedMemorySize, mlp_smem);
    mlp_kernel<<<BB * SS / (8 * MLP_G), MLP_T, mlp_smem>>>(
        xyz, feat,
        a[0], a[1], a[2], a[3], a[4], a[5],
        a[6], a[7], a[8], a[9], a[10], a[11],
        a[12], a[13], a[14], a[15], a[16], a[17],
        out_xyz, out_feat);
}